// round 1
// baseline (speedup 1.0000x reference)
#include <cuda_runtime.h>
#include <math.h>

// ---------------- problem constants ----------------
#define Tt   96
#define Bb   64
#define TB   6144      // Tt*Bb
#define DM   1024
#define DG   512
#define HH   256
#define G4   1024      // 4*HH

// ---------------- scratch (device globals; no allocation allowed) ----------------
__device__ float g_U  [TB * DM];          // fused-LN average          (25.2 MB)
__device__ float g_Ul [TB * DG];          // U @ W_l^T + b_l           (12.6 MB)
__device__ float g_h0 [TB * DG];          // layer0 biLSTM output      (12.6 MB)
__device__ float g_xgf[TB * G4];          // input gates, forward dir  (25.2 MB)
__device__ float g_xgb[TB * G4];          // input gates, backward dir (25.2 MB)
__device__ float g_alpha[4 * Bb];         // 0.25 * rsqrt(var+eps) per (tensor,batch)
__device__ float g_shift[4 * Bb];         // alpha * mean
__device__ float g_hbuf[2 * 2 * HH * Bb]; // ping-pong h state [buf][dir][k][b]
__device__ unsigned           g_bar_count;
__device__ unsigned long long g_bar_gen;

// ---------------- LN2 statistics: one block per (tensor i, batch b) ----------------
__global__ void stats_kernel(const float* __restrict__ r1, const float* __restrict__ r2,
                             const float* __restrict__ r3, const float* __restrict__ r4)
{
    int i = blockIdx.x >> 6;
    int b = blockIdx.x & 63;
    const float* r = (i == 0) ? r1 : (i == 1) ? r2 : (i == 2) ? r3 : r4;

    float s = 0.f, q = 0.f;
    const float4* base = (const float4*)(r + (size_t)b * DM);
    for (int t = 0; t < Tt; t++) {
        float4 v = base[(size_t)t * (Bb * DM / 4) + threadIdx.x];
        s += v.x + v.y + v.z + v.w;
        q += v.x * v.x + v.y * v.y + v.z * v.z + v.w * v.w;
    }
    __shared__ float ss[256], sq[256];
    ss[threadIdx.x] = s; sq[threadIdx.x] = q;
    __syncthreads();
    for (int st = 128; st > 0; st >>= 1) {
        if (threadIdx.x < st) {
            ss[threadIdx.x] += ss[threadIdx.x + st];
            sq[threadIdx.x] += sq[threadIdx.x + st];
        }
        __syncthreads();
    }
    if (threadIdx.x == 0) {
        const float inv_n = 1.f / (float)(Tt * DM);
        float m   = ss[0] * inv_n;
        float var = sq[0] * inv_n - m * m;
        float a   = 0.25f * rsqrtf(var + 1e-5f);
        g_alpha[i * Bb + b] = a;
        g_shift[i * Bb + b] = a * m;
    }
}

// ---------------- fused U = mean of 4 layer-normed tensors ----------------
__global__ void build_u_kernel(const float* __restrict__ r1, const float* __restrict__ r2,
                               const float* __restrict__ r3, const float* __restrict__ r4)
{
    size_t idx = (size_t)blockIdx.x * blockDim.x + threadIdx.x;   // float4 index
    size_t e   = idx * 4;
    int b = (int)((e >> 10) & 63);
    float a1 = g_alpha[b], a2 = g_alpha[64 + b], a3 = g_alpha[128 + b], a4 = g_alpha[192 + b];
    float sh = g_shift[b] + g_shift[64 + b] + g_shift[128 + b] + g_shift[192 + b];
    float4 v1 = ((const float4*)r1)[idx];
    float4 v2 = ((const float4*)r2)[idx];
    float4 v3 = ((const float4*)r3)[idx];
    float4 v4 = ((const float4*)r4)[idx];
    float4 o;
    o.x = a1 * v1.x + a2 * v2.x + a3 * v3.x + a4 * v4.x - sh;
    o.y = a1 * v1.y + a2 * v2.y + a3 * v3.y + a4 * v4.y - sh;
    o.z = a1 * v1.z + a2 * v2.z + a3 * v3.z + a4 * v4.z - sh;
    o.w = a1 * v1.w + a2 * v2.w + a3 * v3.w + a4 * v4.w - sh;
    ((float4*)g_U)[idx] = o;
}

// ---------------- SGEMM: C[M,N] = A[M,K] @ W[N,K]^T + bias1 (+bias2) ----------------
// GRAPHIFY=1 remaps output row m=(t*B+b) -> b*T+t (simple_batch_graphify).
__device__ __forceinline__ float4 ld_guard(const float* p, int k, int K)
{
    if (k + 3 < K) return *(const float4*)p;
    float4 v;
    v.x = (k     < K) ? p[0] : 0.f;
    v.y = (k + 1 < K) ? p[1] : 0.f;
    v.z = (k + 2 < K) ? p[2] : 0.f;
    v.w = (k + 3 < K) ? p[3] : 0.f;
    return v;
}

template <int GRAPHIFY>
__global__ void __launch_bounds__(256) sgemm_kernel(
    const float* __restrict__ A, const float* __restrict__ W,
    const float* __restrict__ bias1, const float* __restrict__ bias2,
    float* __restrict__ C, int M, int N, int K, int ldc, int coloff)
{
    constexpr int BM = 128, BN = 64, BK = 8;
    __shared__ float sA[BK][BM];
    __shared__ float sB[BK][BN];

    const int tid = threadIdx.x;
    const int m0 = blockIdx.y * BM, n0 = blockIdx.x * BN;
    const int arow = tid >> 1,           acol = (tid & 1) * 4;
    const int wrow = (tid & 127) >> 1,   wcol = (tid & 1) * 4;
    const int tx = tid & 15, ty = tid >> 4;   // 16x16 threads, 8x4 micro-tile

    float acc[8][4];
#pragma unroll
    for (int i = 0; i < 8; i++)
#pragma unroll
        for (int j = 0; j < 4; j++) acc[i][j] = 0.f;

    const int ktiles = (K + BK - 1) / BK;
    float4 va, vw;
    va = ld_guard(A + (size_t)(m0 + arow) * K + acol, acol, K);
    if (tid < 128) vw = ld_guard(W + (size_t)(n0 + wrow) * K + wcol, wcol, K);

    for (int kt = 0; kt < ktiles; kt++) {
        sA[acol + 0][arow] = va.x; sA[acol + 1][arow] = va.y;
        sA[acol + 2][arow] = va.z; sA[acol + 3][arow] = va.w;
        if (tid < 128) {
            sB[wcol + 0][wrow] = vw.x; sB[wcol + 1][wrow] = vw.y;
            sB[wcol + 2][wrow] = vw.z; sB[wcol + 3][wrow] = vw.w;
        }
        __syncthreads();

        if (kt + 1 < ktiles) {                       // prefetch next tile into regs
            int k0 = (kt + 1) * BK;
            va = ld_guard(A + (size_t)(m0 + arow) * K + k0 + acol, k0 + acol, K);
            if (tid < 128) vw = ld_guard(W + (size_t)(n0 + wrow) * K + k0 + wcol, k0 + wcol, K);
        }

#pragma unroll
        for (int k = 0; k < BK; k++) {
            float4 a0 = *(const float4*)&sA[k][ty * 8];
            float4 a1 = *(const float4*)&sA[k][ty * 8 + 4];
            float4 bf = *(const float4*)&sB[k][tx * 4];
            float am[8] = {a0.x, a0.y, a0.z, a0.w, a1.x, a1.y, a1.z, a1.w};
            float bn[4] = {bf.x, bf.y, bf.z, bf.w};
#pragma unroll
            for (int i = 0; i < 8; i++)
#pragma unroll
                for (int j = 0; j < 4; j++)
                    acc[i][j] += am[i] * bn[j];
        }
        __syncthreads();
    }

    float bb[4];
#pragma unroll
    for (int j = 0; j < 4; j++) {
        int n = n0 + tx * 4 + j;
        bb[j] = bias1[n] + (bias2 ? bias2[n] : 0.f);
    }
#pragma unroll
    for (int i = 0; i < 8; i++) {
        int m = m0 + ty * 8 + i;
        int row = GRAPHIFY ? ((m & 63) * Tt + (m >> 6)) : m;
        float4 o = make_float4(acc[i][0] + bb[0], acc[i][1] + bb[1],
                               acc[i][2] + bb[2], acc[i][3] + bb[3]);
        *(float4*)(C + (size_t)row * ldc + coloff + n0 + tx * 4) = o;
    }
}

// ---------------- software grid barrier (all 128 blocks co-resident) ----------------
__device__ __forceinline__ void grid_barrier(unsigned long long target)
{
    __syncthreads();
    if (threadIdx.x == 0) {
        __threadfence();
        unsigned old = atomicAdd(&g_bar_count, 1u);
        if (old == gridDim.x - 1) {
            atomicExch(&g_bar_count, 0u);
            __threadfence();
            atomicAdd(&g_bar_gen, 1ULL);
        } else {
            while (*(volatile unsigned long long*)&g_bar_gen < target) {
                __nanosleep(32);
            }
        }
        __threadfence();
    }
    __syncthreads();
}

// ---------------- persistent bidirectional LSTM layer ----------------
// grid = 128 blocks: blockIdx>>6 = dir, &63 = blk (4 hidden units each).
// thread: kq = tid&3 (k quarter), slot = tid>>2; u = slot&3, bq = slot>>2 (4 batches).
__global__ void __launch_bounds__(256) lstm_kernel(
    const float* __restrict__ xgf, const float* __restrict__ xgb,
    const float* __restrict__ Whhf, const float* __restrict__ Whhb,
    float* __restrict__ outp, int ldo, int coloff, int graphify)
{
    extern __shared__ float smem[];
    float*  sH  = smem;                        // [k][b] : 256*64 floats (64 KB)
    float4* sW4 = (float4*)(smem + HH * Bb);   // [4 units][257 k] of gate-float4 (16.4 KB)

    const int tid  = threadIdx.x;
    const int dir  = blockIdx.x >> 6;
    const int blk  = blockIdx.x & 63;
    const int kq   = tid & 3;
    const int slot = tid >> 2;
    const int u    = slot & 3;
    const int bq   = slot >> 2;
    const int b0   = bq * 4;
    const int n    = blk * 4 + u;

    const float* xg  = dir ? xgb : xgf;
    const float* Whh = dir ? Whhb : Whhf;

    // load Whh slice for this block's 4 units, all 4 gates packed per (u,k)
    for (int idx = tid; idx < 4 * HH; idx += 256) {
        int uu = idx >> 8, k = idx & 255;
        int nn = blk * 4 + uu;
        float4 w;
        w.x = Whh[(size_t)(0 * HH + nn) * HH + k];   // i
        w.y = Whh[(size_t)(1 * HH + nn) * HH + k];   // f
        w.z = Whh[(size_t)(2 * HH + nn) * HH + k];   // g
        w.w = Whh[(size_t)(3 * HH + nn) * HH + k];   // o
        sW4[uu * 257 + k] = w;
    }

    unsigned long long tgt = *(volatile unsigned long long*)&g_bar_gen;

    // zero the initial h state (buffer 0) for this block's 4 hidden rows
    if (tid < 64) {
        int uu = tid >> 4, bb4 = (tid & 15) * 4;
        *(float4*)(g_hbuf + ((size_t)(0 * 2 + dir) * HH + (blk * 4 + uu)) * Bb + bb4) =
            make_float4(0.f, 0.f, 0.f, 0.f);
    }

    float c[4] = {0.f, 0.f, 0.f, 0.f};
    grid_barrier(++tgt);

    for (int step = 0; step < Tt; step++) {
        const int t   = dir ? (Tt - 1 - step) : step;
        const int cur = step & 1;

        // stage previous h (this direction) into shared, k-major
        const float4* src = (const float4*)(g_hbuf + (size_t)(cur * 2 + dir) * HH * Bb);
        float4* dst = (float4*)sH;
#pragma unroll
        for (int i = 0; i < 16; i++) dst[tid + i * 256] = src[tid + i * 256];
        __syncthreads();

        float4 acc[4];
#pragma unroll
        for (int i = 0; i < 4; i++) acc[i] = make_float4(0.f, 0.f, 0.f, 0.f);

        const float4* wrow = sW4 + u * 257 + kq * 64;
        const float4* h4p  = ((const float4*)sH) + (kq * 64) * 16 + bq;
#pragma unroll 8
        for (int kk = 0; kk < 64; kk++) {
            float4 h4 = h4p[kk * 16];
            float4 w4 = wrow[kk];
            acc[0].x += h4.x * w4.x; acc[0].y += h4.x * w4.y; acc[0].z += h4.x * w4.z; acc[0].w += h4.x * w4.w;
            acc[1].x += h4.y * w4.x; acc[1].y += h4.y * w4.y; acc[1].z += h4.y * w4.z; acc[1].w += h4.y * w4.w;
            acc[2].x += h4.z * w4.x; acc[2].y += h4.z * w4.y; acc[2].z += h4.z * w4.z; acc[2].w += h4.z * w4.w;
            acc[3].x += h4.w * w4.x; acc[3].y += h4.w * w4.y; acc[3].z += h4.w * w4.z; acc[3].w += h4.w * w4.w;
        }

        // reduce k-quarters (lanes kq=0..3 are adjacent)
#pragma unroll
        for (int i = 0; i < 4; i++) {
            acc[i].x += __shfl_xor_sync(0xffffffffu, acc[i].x, 1);
            acc[i].x += __shfl_xor_sync(0xffffffffu, acc[i].x, 2);
            acc[i].y += __shfl_xor_sync(0xffffffffu, acc[i].y, 1);
            acc[i].y += __shfl_xor_sync(0xffffffffu, acc[i].y, 2);
            acc[i].z += __shfl_xor_sync(0xffffffffu, acc[i].z, 1);
            acc[i].z += __shfl_xor_sync(0xffffffffu, acc[i].z, 2);
            acc[i].w += __shfl_xor_sync(0xffffffffu, acc[i].w, 1);
            acc[i].w += __shfl_xor_sync(0xffffffffu, acc[i].w, 2);
        }

        if (kq == 0) {
            const float* xp = xg + (size_t)t * Bb * G4;
            float hn[4];
#pragma unroll
            for (int i = 0; i < 4; i++) {
                const float* p = xp + (size_t)(b0 + i) * G4;
                float gi = acc[i].x + p[n];
                float gf = acc[i].y + p[HH + n];
                float gg = acc[i].z + p[2 * HH + n];
                float go = acc[i].w + p[3 * HH + n];
                float si = 1.f / (1.f + expf(-gi));
                float sf = 1.f / (1.f + expf(-gf));
                float so = 1.f / (1.f + expf(-go));
                c[i] = sf * c[i] + si * tanhf(gg);
                float h = so * tanhf(c[i]);
                hn[i] = h;
                int row = graphify ? ((b0 + i) * Tt + t) : (t * Bb + b0 + i);
                outp[(size_t)row * ldo + coloff + dir * HH + n] = h;
            }
            *(float4*)(g_hbuf + ((size_t)((1 - cur) * 2 + dir) * HH + n) * Bb + b0) =
                make_float4(hn[0], hn[1], hn[2], hn[3]);
        }
        grid_barrier(++tgt);
    }
}

// ---------------- launch ----------------
extern "C" void kernel_launch(void* const* d_in, const int* in_sizes, int n_in,
                              void* d_out, int out_size)
{
    const float* r1  = (const float*)d_in[0];
    const float* r2  = (const float*)d_in[1];
    const float* r3  = (const float*)d_in[2];
    const float* r4  = (const float*)d_in[3];
    const float* U_a = (const float*)d_in[4];
    const float* U_v = (const float*)d_in[5];
    // d_in[6] = seq_lengths (full, unused)
    const float* W_a = (const float*)d_in[7];
    const float* b_a = (const float*)d_in[8];
    const float* W_v = (const float*)d_in[9];
    const float* b_v = (const float*)d_in[10];
    const float* W_l = (const float*)d_in[11];
    const float* b_l = (const float*)d_in[12];
    const float* Wih0f = (const float*)d_in[13];
    const float* Whh0f = (const float*)d_in[14];
    const float* bih0f = (const float*)d_in[15];
    const float* bhh0f = (const float*)d_in[16];
    const float* Wih0b = (const float*)d_in[17];
    const float* Whh0b = (const float*)d_in[18];
    const float* bih0b = (const float*)d_in[19];
    const float* bhh0b = (const float*)d_in[20];
    const float* Wih1f = (const float*)d_in[21];
    const float* Whh1f = (const float*)d_in[22];
    const float* bih1f = (const float*)d_in[23];
    const float* bhh1f = (const float*)d_in[24];
    const float* Wih1b = (const float*)d_in[25];
    const float* Whh1b = (const float*)d_in[26];
    const float* bih1b = (const float*)d_in[27];
    const float* bhh1b = (const float*)d_in[28];
    float* out = (float*)d_out;

    float *pU, *pUl, *ph0, *pxf, *pxb;
    cudaGetSymbolAddress((void**)&pU,  g_U);
    cudaGetSymbolAddress((void**)&pUl, g_Ul);
    cudaGetSymbolAddress((void**)&ph0, g_h0);
    cudaGetSymbolAddress((void**)&pxf, g_xgf);
    cudaGetSymbolAddress((void**)&pxb, g_xgb);

    // LN2 stats + fused U
    stats_kernel<<<256, 256>>>(r1, r2, r3, r4);
    build_u_kernel<<<TB * DM / 4 / 256, 256>>>(r1, r2, r3, r4);

    dim3 g512(DG / 64, TB / 128);
    dim3 g1024(G4 / 64, TB / 128);

    // emotions_a / emotions_v straight into the output (graphify fused in epilogue)
    sgemm_kernel<1><<<g512, 256>>>(U_a, W_a, b_a, nullptr, out, TB, DG, 100,  1536, 0);
    sgemm_kernel<1><<<g512, 256>>>(U_v, W_v, b_v, nullptr, out, TB, DG, 512,  1536, 512);
    // Ul = U @ W_l^T + b_l
    sgemm_kernel<0><<<g512, 256>>>(pU, W_l, b_l, nullptr, pUl, TB, DG, 1024, 512, 0);

    // LSTM layer 0: input-gate GEMMs then persistent recurrence
    sgemm_kernel<0><<<g1024, 256>>>(pUl, Wih0f, bih0f, bhh0f, pxf, TB, G4, 512, 1024, 0);
    sgemm_kernel<0><<<g1024, 256>>>(pUl, Wih0b, bih0b, bhh0b, pxb, TB, G4, 512, 1024, 0);

    const int lstm_smem = (HH * Bb) * 4 + 4 * 257 * 16;   // 81984 bytes
    cudaFuncSetAttribute(lstm_kernel, cudaFuncAttributeMaxDynamicSharedMemorySize, lstm_smem);
    lstm_kernel<<<128, 256, lstm_smem>>>(pxf, pxb, Whh0f, Whh0b, ph0, 512, 0, 0);

    // LSTM layer 1 (input = layer0 output), writes features_l into out cols [1024,1536)
    sgemm_kernel<0><<<g1024, 256>>>(ph0, Wih1f, bih1f, bhh1f, pxf, TB, G4, 512, 1024, 0);
    sgemm_kernel<0><<<g1024, 256>>>(ph0, Wih1b, bih1b, bhh1b, pxb, TB, G4, 512, 1024, 0);
    lstm_kernel<<<128, 256, lstm_smem>>>(pxf, pxb, Whh1f, Whh1b, out, 1536, 1024, 1);
}

// round 2
// speedup vs baseline: 1.3049x; 1.3049x over previous
#include <cuda_runtime.h>
#include <math.h>
#include <stdint.h>

// ---------------- problem constants ----------------
#define Tt   96
#define Bb   64
#define TB   6144      // Tt*Bb
#define DM   1024
#define DG   512
#define HH   256
#define G4   1024      // 4*HH

// ---------------- scratch (device globals; no allocation allowed) ----------------
__device__ float g_U  [TB * DM];
__device__ float g_Ul [TB * DG];
__device__ float g_h0 [TB * DG];
__device__ float g_xgf[TB * G4];
__device__ float g_xgb[TB * G4];
__device__ float g_alpha[4 * Bb];
__device__ float g_shift[4 * Bb];

// ---------------- LN2 statistics: one block per (tensor i, batch b) ----------------
__global__ void stats_kernel(const float* __restrict__ r1, const float* __restrict__ r2,
                             const float* __restrict__ r3, const float* __restrict__ r4)
{
    int i = blockIdx.x >> 6;
    int b = blockIdx.x & 63;
    const float* r = (i == 0) ? r1 : (i == 1) ? r2 : (i == 2) ? r3 : r4;

    float s = 0.f, q = 0.f;
    const float4* base = (const float4*)(r + (size_t)b * DM);
    for (int t = 0; t < Tt; t++) {
        float4 v = base[(size_t)t * (Bb * DM / 4) + threadIdx.x];
        s += v.x + v.y + v.z + v.w;
        q += v.x * v.x + v.y * v.y + v.z * v.z + v.w * v.w;
    }
    __shared__ float ss[256], sq[256];
    ss[threadIdx.x] = s; sq[threadIdx.x] = q;
    __syncthreads();
    for (int st = 128; st > 0; st >>= 1) {
        if (threadIdx.x < st) {
            ss[threadIdx.x] += ss[threadIdx.x + st];
            sq[threadIdx.x] += sq[threadIdx.x + st];
        }
        __syncthreads();
    }
    if (threadIdx.x == 0) {
        const float inv_n = 1.f / (float)(Tt * DM);
        float m   = ss[0] * inv_n;
        float var = sq[0] * inv_n - m * m;
        float a   = 0.25f * rsqrtf(var + 1e-5f);
        g_alpha[i * Bb + b] = a;
        g_shift[i * Bb + b] = a * m;
    }
}

// ---------------- fused U = mean of 4 layer-normed tensors ----------------
__global__ void build_u_kernel(const float* __restrict__ r1, const float* __restrict__ r2,
                               const float* __restrict__ r3, const float* __restrict__ r4)
{
    size_t idx = (size_t)blockIdx.x * blockDim.x + threadIdx.x;   // float4 index
    size_t e   = idx * 4;
    int b = (int)((e >> 10) & 63);
    float a1 = g_alpha[b], a2 = g_alpha[64 + b], a3 = g_alpha[128 + b], a4 = g_alpha[192 + b];
    float sh = g_shift[b] + g_shift[64 + b] + g_shift[128 + b] + g_shift[192 + b];
    float4 v1 = ((const float4*)r1)[idx];
    float4 v2 = ((const float4*)r2)[idx];
    float4 v3 = ((const float4*)r3)[idx];
    float4 v4 = ((const float4*)r4)[idx];
    float4 o;
    o.x = a1 * v1.x + a2 * v2.x + a3 * v3.x + a4 * v4.x - sh;
    o.y = a1 * v1.y + a2 * v2.y + a3 * v3.y + a4 * v4.y - sh;
    o.z = a1 * v1.z + a2 * v2.z + a3 * v3.z + a4 * v4.z - sh;
    o.w = a1 * v1.w + a2 * v2.w + a3 * v3.w + a4 * v4.w - sh;
    ((float4*)g_U)[idx] = o;
}

// ---------------- SGEMM: C[M,N] = A[M,K] @ W[N,K]^T + bias1 (+bias2) ----------------
__device__ __forceinline__ float4 ld_guard(const float* p, int k, int K)
{
    if (k + 3 < K) return *(const float4*)p;
    float4 v;
    v.x = (k     < K) ? p[0] : 0.f;
    v.y = (k + 1 < K) ? p[1] : 0.f;
    v.z = (k + 2 < K) ? p[2] : 0.f;
    v.w = (k + 3 < K) ? p[3] : 0.f;
    return v;
}

template <int GRAPHIFY>
__global__ void __launch_bounds__(256) sgemm_kernel(
    const float* __restrict__ A, const float* __restrict__ W,
    const float* __restrict__ bias1, const float* __restrict__ bias2,
    float* __restrict__ C, int M, int N, int K, int ldc, int coloff)
{
    constexpr int BM = 128, BN = 128, BK = 16, PAD = 4;
    __shared__ __align__(16) float sA[2][BK][BM + PAD];
    __shared__ __align__(16) float sB[2][BK][BN + PAD];

    const int tid = threadIdx.x;
    const int m0 = blockIdx.y * BM, n0 = blockIdx.x * BN;
    const int tx = tid & 15, ty = tid >> 4;          // 16x16 threads, 8x8 micro-tile
    const int row0 = tid >> 2;                       // 0..63
    const int c4   = (tid & 3) * 4;                  // k offset 0,4,8,12

    float acc[8][8];
#pragma unroll
    for (int i = 0; i < 8; i++)
#pragma unroll
        for (int j = 0; j < 8; j++) acc[i][j] = 0.f;

    const int ktiles = (K + BK - 1) / BK;
    float4 va0, va1, vb0, vb1;

    va0 = ld_guard(A + (size_t)(m0 + row0     ) * K + c4, c4, K);
    va1 = ld_guard(A + (size_t)(m0 + row0 + 64) * K + c4, c4, K);
    vb0 = ld_guard(W + (size_t)(n0 + row0     ) * K + c4, c4, K);
    vb1 = ld_guard(W + (size_t)(n0 + row0 + 64) * K + c4, c4, K);

    int cur = 0;
    {
        sA[0][c4+0][row0] = va0.x; sA[0][c4+1][row0] = va0.y; sA[0][c4+2][row0] = va0.z; sA[0][c4+3][row0] = va0.w;
        sA[0][c4+0][row0+64] = va1.x; sA[0][c4+1][row0+64] = va1.y; sA[0][c4+2][row0+64] = va1.z; sA[0][c4+3][row0+64] = va1.w;
        sB[0][c4+0][row0] = vb0.x; sB[0][c4+1][row0] = vb0.y; sB[0][c4+2][row0] = vb0.z; sB[0][c4+3][row0] = vb0.w;
        sB[0][c4+0][row0+64] = vb1.x; sB[0][c4+1][row0+64] = vb1.y; sB[0][c4+2][row0+64] = vb1.z; sB[0][c4+3][row0+64] = vb1.w;
    }
    __syncthreads();

    for (int kt = 0; kt < ktiles; kt++) {
        const bool more = (kt + 1 < ktiles);
        if (more) {
            int k0 = (kt + 1) * BK + c4;
            va0 = ld_guard(A + (size_t)(m0 + row0     ) * K + k0, k0, K);
            va1 = ld_guard(A + (size_t)(m0 + row0 + 64) * K + k0, k0, K);
            vb0 = ld_guard(W + (size_t)(n0 + row0     ) * K + k0, k0, K);
            vb1 = ld_guard(W + (size_t)(n0 + row0 + 64) * K + k0, k0, K);
        }

#pragma unroll
        for (int k = 0; k < BK; k++) {
            float4 a0 = *(const float4*)&sA[cur][k][ty * 8];
            float4 a1 = *(const float4*)&sA[cur][k][ty * 8 + 4];
            float4 b0 = *(const float4*)&sB[cur][k][tx * 8];
            float4 b1 = *(const float4*)&sB[cur][k][tx * 8 + 4];
            float am[8] = {a0.x, a0.y, a0.z, a0.w, a1.x, a1.y, a1.z, a1.w};
            float bn[8] = {b0.x, b0.y, b0.z, b0.w, b1.x, b1.y, b1.z, b1.w};
#pragma unroll
            for (int i = 0; i < 8; i++)
#pragma unroll
                for (int j = 0; j < 8; j++)
                    acc[i][j] += am[i] * bn[j];
        }

        if (more) {
            int nb = cur ^ 1;
            sA[nb][c4+0][row0] = va0.x; sA[nb][c4+1][row0] = va0.y; sA[nb][c4+2][row0] = va0.z; sA[nb][c4+3][row0] = va0.w;
            sA[nb][c4+0][row0+64] = va1.x; sA[nb][c4+1][row0+64] = va1.y; sA[nb][c4+2][row0+64] = va1.z; sA[nb][c4+3][row0+64] = va1.w;
            sB[nb][c4+0][row0] = vb0.x; sB[nb][c4+1][row0] = vb0.y; sB[nb][c4+2][row0] = vb0.z; sB[nb][c4+3][row0] = vb0.w;
            sB[nb][c4+0][row0+64] = vb1.x; sB[nb][c4+1][row0+64] = vb1.y; sB[nb][c4+2][row0+64] = vb1.z; sB[nb][c4+3][row0+64] = vb1.w;
        }
        __syncthreads();
        cur ^= 1;
    }

    float bb[8];
#pragma unroll
    for (int j = 0; j < 8; j++) {
        int nn = n0 + tx * 8 + j;
        bb[j] = bias1[nn] + (bias2 ? bias2[nn] : 0.f);
    }
#pragma unroll
    for (int i = 0; i < 8; i++) {
        int m = m0 + ty * 8 + i;
        int row = GRAPHIFY ? ((m & 63) * Tt + (m >> 6)) : m;
        float* cp = C + (size_t)row * ldc + coloff + n0 + tx * 8;
        float4 o0 = make_float4(acc[i][0] + bb[0], acc[i][1] + bb[1], acc[i][2] + bb[2], acc[i][3] + bb[3]);
        float4 o1 = make_float4(acc[i][4] + bb[4], acc[i][5] + bb[5], acc[i][6] + bb[6], acc[i][7] + bb[7]);
        *(float4*)cp = o0;
        *(float4*)(cp + 4) = o1;
    }
}

// ---------------- cluster-based bidirectional LSTM ----------------
// 16 clusters of 8 CTAs. cluster = (dir, 8-batch group). CTA rank owns 32 hidden
// units (all 4 gates, full k=256 of Whh in smem, 132KB). Per step: each thread
// computes one (unit, batch) cell, pushes h to all 8 peers via DSMEM, cluster sync.
#define SW_FLOATS (256 * 33 * 4)        // float4[k*33+u], padded
#define SH_FLOATS (2 * 2048)            // double-buffered h: [buf][k][b]
#define LSTM_SMEM ((SW_FLOATS + SH_FLOATS) * 4)

__device__ __forceinline__ uint32_t smem_u32(const void* p)
{
    uint32_t a;
    asm("{ .reg .u64 t; cvta.to.shared.u64 t, %1; cvt.u32.u64 %0, t; }" : "=r"(a) : "l"(p));
    return a;
}

#define CLUSTER_SYNC() do { \
    asm volatile("barrier.cluster.arrive.aligned;" ::: "memory"); \
    asm volatile("barrier.cluster.wait.aligned;"   ::: "memory"); \
} while (0)

__global__ void __launch_bounds__(256, 1) __cluster_dims__(8, 1, 1)
lstm_kernel(const float* __restrict__ xgf, const float* __restrict__ xgb,
            const float* __restrict__ Whhf, const float* __restrict__ Whhb,
            float* __restrict__ outp, int ldo, int coloff, int graphify)
{
    extern __shared__ float smem[];
    float4* sW = (float4*)smem;                 // [k*33 + u]
    float*  sH = smem + SW_FLOATS;              // [buf][k][b] : buf*2048 + k*8 + b

    const int tid = threadIdx.x;
    uint32_t rank;
    asm("mov.u32 %0, %%cluster_ctarank;" : "=r"(rank));
    const int dir  = blockIdx.x >> 6;
    const int bgrp = (blockIdx.x >> 3) & 7;
    const int b    = tid & 7;
    const int u    = tid >> 3;                  // 0..31
    const int n    = (int)rank * 32 + u;        // hidden unit 0..255
    const int bglob = bgrp * 8 + b;

    const float* xg  = dir ? xgb : xgf;
    const float* Whh = dir ? Whhb : Whhf;

    // stage this CTA's Whh slice: sW[k*33+u] = {Wi, Wf, Wg, Wo}[n=rank*32+u][k]
#pragma unroll 4
    for (int it = 0; it < 32; it++) {
        int idx = it * 256 + tid;
        int uu  = (idx >> 3) & 31;
        int kk  = (idx & 7) | ((idx >> 8) << 3);
        int nn  = (int)rank * 32 + uu;
        float4 w;
        w.x = Whh[(size_t)(       nn) * HH + kk];
        w.y = Whh[(size_t)(HH   + nn) * HH + kk];
        w.z = Whh[(size_t)(2*HH + nn) * HH + kk];
        w.w = Whh[(size_t)(3*HH + nn) * HH + kk];
        sW[kk * 33 + uu] = w;
    }
    // zero both h buffers
    for (int i = tid; i < SH_FLOATS; i += 256) sH[i] = 0.f;

    const uint32_t sm_base = smem_u32(smem);
    const uint32_t hslot   = sm_base + (uint32_t)(SW_FLOATS + n * 8 + b) * 4u;

    CLUSTER_SYNC();

    float c = 0.f;
    for (int step = 0; step < Tt; step++) {
        const int t    = dir ? (Tt - 1 - step) : step;
        const int rbuf = step & 1;
        const int wbuf = rbuf ^ 1;

        // prefetch x gates (overlap with recurrent GEMM below)
        const float* xp = xg + ((size_t)t * Bb + bglob) * G4 + n;
        float xi = xp[0], xf = xp[HH], xgv = xp[2 * HH], xo = xp[3 * HH];

        const float*  hp = sH + rbuf * 2048 + b;
        const float4* wp = sW + u;

        unsigned long long accIF = 0ull, accGO = 0ull;   // packed (i,f), (g,o)
#pragma unroll 16
        for (int k = 0; k < HH; k++) {
            float h = hp[k * 8];
            longlong2 wv = *(const longlong2*)(wp + k * 33);  // .x=(Wi,Wf) .y=(Wg,Wo)
            unsigned hb = __float_as_uint(h);
            unsigned long long hh;
            asm("mov.b64 %0, {%1, %1};" : "=l"(hh) : "r"(hb));
            asm("fma.rn.f32x2 %0, %1, %2, %0;" : "+l"(accIF) : "l"(hh), "l"((unsigned long long)wv.x));
            asm("fma.rn.f32x2 %0, %1, %2, %0;" : "+l"(accGO) : "l"(hh), "l"((unsigned long long)wv.y));
        }
        unsigned ri, rf, rg, ro;
        asm("mov.b64 {%0, %1}, %2;" : "=r"(ri), "=r"(rf) : "l"(accIF));
        asm("mov.b64 {%0, %1}, %2;" : "=r"(rg), "=r"(ro) : "l"(accGO));

        float gi = __uint_as_float(ri) + xi;
        float gf = __uint_as_float(rf) + xf;
        float gg = __uint_as_float(rg) + xgv;
        float go = __uint_as_float(ro) + xo;
        float si = 1.f / (1.f + expf(-gi));
        float sf = 1.f / (1.f + expf(-gf));
        float so = 1.f / (1.f + expf(-go));
        c = sf * c + si * tanhf(gg);
        float h = so * tanhf(c);

        int row = graphify ? (bglob * Tt + t) : (t * Bb + bglob);
        outp[(size_t)row * ldo + coloff + dir * HH + n] = h;

        // broadcast h to all 8 CTAs' write buffer via DSMEM
        uint32_t dst = hslot + (uint32_t)(wbuf * 2048) * 4u;
#pragma unroll
        for (int r2 = 0; r2 < 8; r2++) {
            uint32_t ra;
            asm("mapa.shared::cluster.u32 %0, %1, %2;" : "=r"(ra) : "r"(dst), "r"(r2));
            asm volatile("st.shared::cluster.f32 [%0], %1;" :: "r"(ra), "f"(h));
        }
        CLUSTER_SYNC();
    }
}

// ---------------- launch ----------------
extern "C" void kernel_launch(void* const* d_in, const int* in_sizes, int n_in,
                              void* d_out, int out_size)
{
    const float* r1  = (const float*)d_in[0];
    const float* r2  = (const float*)d_in[1];
    const float* r3  = (const float*)d_in[2];
    const float* r4  = (const float*)d_in[3];
    const float* U_a = (const float*)d_in[4];
    const float* U_v = (const float*)d_in[5];
    const float* W_a = (const float*)d_in[7];
    const float* b_a = (const float*)d_in[8];
    const float* W_v = (const float*)d_in[9];
    const float* b_v = (const float*)d_in[10];
    const float* W_l = (const float*)d_in[11];
    const float* b_l = (const float*)d_in[12];
    const float* Wih0f = (const float*)d_in[13];
    const float* Whh0f = (const float*)d_in[14];
    const float* bih0f = (const float*)d_in[15];
    const float* bhh0f = (const float*)d_in[16];
    const float* Wih0b = (const float*)d_in[17];
    const float* Whh0b = (const float*)d_in[18];
    const float* bih0b = (const float*)d_in[19];
    const float* bhh0b = (const float*)d_in[20];
    const float* Wih1f = (const float*)d_in[21];
    const float* Whh1f = (const float*)d_in[22];
    const float* bih1f = (const float*)d_in[23];
    const float* bhh1f = (const float*)d_in[24];
    const float* Wih1b = (const float*)d_in[25];
    const float* Whh1b = (const float*)d_in[26];
    const float* bih1b = (const float*)d_in[27];
    const float* bhh1b = (const float*)d_in[28];
    float* out = (float*)d_out;

    float *pU, *pUl, *ph0, *pxf, *pxb;
    cudaGetSymbolAddress((void**)&pU,  g_U);
    cudaGetSymbolAddress((void**)&pUl, g_Ul);
    cudaGetSymbolAddress((void**)&ph0, g_h0);
    cudaGetSymbolAddress((void**)&pxf, g_xgf);
    cudaGetSymbolAddress((void**)&pxb, g_xgb);

    stats_kernel<<<256, 256>>>(r1, r2, r3, r4);
    build_u_kernel<<<TB * DM / 4 / 256, 256>>>(r1, r2, r3, r4);

    dim3 g512(DG / 128, TB / 128);
    dim3 g1024(G4 / 128, TB / 128);

    // emotions_a / emotions_v straight into output (graphify in epilogue)
    sgemm_kernel<1><<<g512, 256>>>(U_a, W_a, b_a, nullptr, out, TB, DG, 100,  1536, 0);
    sgemm_kernel<1><<<g512, 256>>>(U_v, W_v, b_v, nullptr, out, TB, DG, 512,  1536, 512);
    // Ul = U @ W_l^T + b_l
    sgemm_kernel<0><<<g512, 256>>>(pU, W_l, b_l, nullptr, pUl, TB, DG, 1024, 512, 0);

    // LSTM layer 0
    sgemm_kernel<0><<<g1024, 256>>>(pUl, Wih0f, bih0f, bhh0f, pxf, TB, G4, 512, 1024, 0);
    sgemm_kernel<0><<<g1024, 256>>>(pUl, Wih0b, bih0b, bhh0b, pxb, TB, G4, 512, 1024, 0);

    cudaFuncSetAttribute(lstm_kernel, cudaFuncAttributeMaxDynamicSharedMemorySize, LSTM_SMEM);
    lstm_kernel<<<128, 256, LSTM_SMEM>>>(pxf, pxb, Whh0f, Whh0b, ph0, 512, 0, 0);

    // LSTM layer 1 -> features_l into out cols [1024,1536)
    sgemm_kernel<0><<<g1024, 256>>>(ph0, Wih1f, bih1f, bhh1f, pxf, TB, G4, 512, 1024, 0);
    sgemm_kernel<0><<<g1024, 256>>>(ph0, Wih1b, bih1b, bhh1b, pxb, TB, G4, 512, 1024, 0);
    lstm_kernel<<<128, 256, LSTM_SMEM>>>(pxf, pxb, Whh1f, Whh1b, out, 1536, 1024, 1);
}

// round 4
// speedup vs baseline: 1.6378x; 1.2551x over previous
#include <cuda_runtime.h>
#include <cuda_bf16.h>
#include <math.h>
#include <stdint.h>

// ---------------- problem constants ----------------
#define Tt   96
#define Bb   64
#define TB   6144      // Tt*Bb
#define DM   1024
#define DG   512
#define HH   256
#define G4   1024      // 4*HH

// ---------------- scratch (device globals; no allocation allowed) ----------------
__device__ float g_xgf[TB * G4];
__device__ float g_xgb[TB * G4];
__device__ float g_h0 [TB * DG];
__device__ float g_alpha[4 * Bb];
__device__ float g_shift[4 * Bb];

// bf16 hi/lo pairs
__device__ __nv_bfloat16 g_Uhi[TB * DM],  g_Ulo[TB * DM];     // U (K=1024)
__device__ __nv_bfloat16 g_Uah[TB * 128], g_Ual[TB * 128];    // U_a padded K=100->128
__device__ __nv_bfloat16 g_Uvh[TB * DG],  g_Uvl[TB * DG];     // U_v (K=512)
__device__ __nv_bfloat16 g_Xhi[TB * DG],  g_Xlo[TB * DG];     // Ul pair, then h0 pair
__device__ __nv_bfloat16 g_Wah[DG * 128], g_Wal[DG * 128];
__device__ __nv_bfloat16 g_Wvh[DG * DG],  g_Wvl[DG * DG];
__device__ __nv_bfloat16 g_Wlh[DG * DM],  g_Wll[DG * DM];
__device__ __nv_bfloat16 g_W0fh[G4 * DG], g_W0fl[G4 * DG];
__device__ __nv_bfloat16 g_W0bh[G4 * DG], g_W0bl[G4 * DG];
__device__ __nv_bfloat16 g_W1fh[G4 * DG], g_W1fl[G4 * DG];
__device__ __nv_bfloat16 g_W1bh[G4 * DG], g_W1bl[G4 * DG];

// ---------------- helpers ----------------
__device__ __forceinline__ uint32_t smem_u32(const void* p) {
    uint32_t a;
    asm("{ .reg .u64 t; cvta.to.shared.u64 t, %1; cvt.u32.u64 %0, t; }" : "=r"(a) : "l"(p));
    return a;
}
__device__ __forceinline__ uint32_t lds32(uint32_t addr) {
    uint32_t v;
    asm volatile("ld.shared.b32 %0, [%1];" : "=r"(v) : "r"(addr));
    return v;
}
#define CP16(dst, src) \
    asm volatile("cp.async.cg.shared.global [%0], [%1], 16;" :: "r"(dst), "l"(src))
#define CP_COMMIT() asm volatile("cp.async.commit_group;" ::: "memory")
#define CP_WAIT(n)  asm volatile("cp.async.wait_group %0;" :: "n"(n) : "memory")

#define MMA16816(d, a, b) \
    asm volatile("mma.sync.aligned.m16n8k16.row.col.f32.bf16.bf16.f32 " \
        "{%0,%1,%2,%3}, {%4,%5,%6,%7}, {%8,%9}, {%0,%1,%2,%3};" \
        : "+f"((d)[0]), "+f"((d)[1]), "+f"((d)[2]), "+f"((d)[3]) \
        : "r"((a)[0]), "r"((a)[1]), "r"((a)[2]), "r"((a)[3]), "r"((b)[0]), "r"((b)[1]))

// ---------------- LN2 statistics ----------------
__global__ void stats_kernel(const float* __restrict__ r1, const float* __restrict__ r2,
                             const float* __restrict__ r3, const float* __restrict__ r4)
{
    int i = blockIdx.x >> 6;
    int b = blockIdx.x & 63;
    const float* r = (i == 0) ? r1 : (i == 1) ? r2 : (i == 2) ? r3 : r4;
    float s = 0.f, q = 0.f;
    const float4* base = (const float4*)(r + (size_t)b * DM);
    for (int t = 0; t < Tt; t++) {
        float4 v = base[(size_t)t * (Bb * DM / 4) + threadIdx.x];
        s += v.x + v.y + v.z + v.w;
        q += v.x * v.x + v.y * v.y + v.z * v.z + v.w * v.w;
    }
    __shared__ float ss[256], sq[256];
    ss[threadIdx.x] = s; sq[threadIdx.x] = q;
    __syncthreads();
    for (int st = 128; st > 0; st >>= 1) {
        if (threadIdx.x < st) { ss[threadIdx.x] += ss[threadIdx.x + st]; sq[threadIdx.x] += sq[threadIdx.x + st]; }
        __syncthreads();
    }
    if (threadIdx.x == 0) {
        const float inv_n = 1.f / (float)(Tt * DM);
        float m   = ss[0] * inv_n;
        float var = sq[0] * inv_n - m * m;
        float a   = 0.25f * rsqrtf(var + 1e-5f);
        g_alpha[i * Bb + b] = a;
        g_shift[i * Bb + b] = a * m;
    }
}

// ---------------- fused U build + bf16 split ----------------
__global__ void build_u_split(const float* __restrict__ r1, const float* __restrict__ r2,
                              const float* __restrict__ r3, const float* __restrict__ r4)
{
    size_t idx = (size_t)blockIdx.x * blockDim.x + threadIdx.x;   // float4 index
    size_t e   = idx * 4;
    int b = (int)((e >> 10) & 63);
    float a1 = g_alpha[b], a2 = g_alpha[64 + b], a3 = g_alpha[128 + b], a4 = g_alpha[192 + b];
    float sh = g_shift[b] + g_shift[64 + b] + g_shift[128 + b] + g_shift[192 + b];
    float4 v1 = ((const float4*)r1)[idx];
    float4 v2 = ((const float4*)r2)[idx];
    float4 v3 = ((const float4*)r3)[idx];
    float4 v4 = ((const float4*)r4)[idx];
    float o[4];
    o[0] = a1 * v1.x + a2 * v2.x + a3 * v3.x + a4 * v4.x - sh;
    o[1] = a1 * v1.y + a2 * v2.y + a3 * v3.y + a4 * v4.y - sh;
    o[2] = a1 * v1.z + a2 * v2.z + a3 * v3.z + a4 * v4.z - sh;
    o[3] = a1 * v1.w + a2 * v2.w + a3 * v3.w + a4 * v4.w - sh;
    __nv_bfloat162 hi0, hi1, lo0, lo1;
    hi0.x = __float2bfloat16(o[0]); hi0.y = __float2bfloat16(o[1]);
    hi1.x = __float2bfloat16(o[2]); hi1.y = __float2bfloat16(o[3]);
    lo0.x = __float2bfloat16(o[0] - __bfloat162float(hi0.x));
    lo0.y = __float2bfloat16(o[1] - __bfloat162float(hi0.y));
    lo1.x = __float2bfloat16(o[2] - __bfloat162float(hi1.x));
    lo1.y = __float2bfloat16(o[3] - __bfloat162float(hi1.y));
    ((__nv_bfloat162*)g_Uhi)[idx * 2]     = hi0;
    ((__nv_bfloat162*)g_Uhi)[idx * 2 + 1] = hi1;
    ((__nv_bfloat162*)g_Ulo)[idx * 2]     = lo0;
    ((__nv_bfloat162*)g_Ulo)[idx * 2 + 1] = lo1;
}

// ---------------- fp32 -> bf16 hi/lo with K padding ----------------
__global__ void convert_pad(const float* __restrict__ in, __nv_bfloat16* __restrict__ hi,
                            __nv_bfloat16* __restrict__ lo, int K, int Kpad, int total)
{
    int idx = blockIdx.x * 256 + threadIdx.x;
    if (idx >= total) return;
    int r = idx / Kpad, c = idx - r * Kpad;
    float v = (c < K) ? in[(size_t)r * K + c] : 0.f;
    __nv_bfloat16 h = __float2bfloat16(v);
    hi[idx] = h;
    lo[idx] = __float2bfloat16(v - __bfloat162float(h));
}

// ---------------- bf16-split GEMM via mma.sync (HMMA) ----------------
// C[M,N] = (Ahi+Alo)[M,K] @ (Bhi+Blo)[N,K]^T + bias1 (+bias2)
// OUTMODE: 0 = fp32 C, 1 = fp32 C with graphify row remap, 2 = bf16 hi/lo pair.
// Block 128x128, 8 warps (4 in M x 2 in N), warp tile 32x64, BK=32, cp.async x2 stages.
#define TPAD  40                          // bf16 row stride (80B, conflict-free)
#define TSZ   (128 * TPAD * 2)            // bytes per tile (10240)
#define SM_BIAS 0
#define SM_TILES 512
#define TILE_OFF(st, mat) (SM_TILES + ((st) * 4 + (mat)) * TSZ)
#define GEMM_SMEM (SM_TILES + 8 * TSZ)    // 82432 bytes

template <int OUTMODE>
__global__ void __launch_bounds__(256, 1) gemm_mma(
    const __nv_bfloat16* __restrict__ Ahi, const __nv_bfloat16* __restrict__ Alo,
    const __nv_bfloat16* __restrict__ Bhi, const __nv_bfloat16* __restrict__ Blo,
    const float* __restrict__ bias1, const float* __restrict__ bias2,
    float* __restrict__ C, __nv_bfloat16* __restrict__ Chi, __nv_bfloat16* __restrict__ Clo,
    int K, int ldc, int coloff)
{
    extern __shared__ char smem[];
    const uint32_t sb = smem_u32(smem);
    const int tid  = threadIdx.x;
    const int lane = tid & 31, wid = tid >> 5;
    const int wm = wid >> 1, wn = wid & 1;
    const int g = lane >> 2, tig = lane & 3;
    const int n0 = blockIdx.x * 128, m0 = blockIdx.y * 128;

    if (tid < 128) {
        float bv = bias1[n0 + tid];
        if (bias2) bv += bias2[n0 + tid];
        *(float*)(smem + SM_BIAS + tid * 4) = bv;
    }

    // per-thread load slots: 2 x 16B per tile per chunk
    const int lr0 = (tid * 2) >> 2,     lc0 = ((tid * 2) & 3) * 8;
    const int lr1 = (tid * 2 + 1) >> 2, lc1 = ((tid * 2 + 1) & 3) * 8;

    float acc[2][8][4];
#pragma unroll
    for (int i = 0; i < 2; i++)
#pragma unroll
        for (int j = 0; j < 8; j++)
#pragma unroll
            for (int x = 0; x < 4; x++) acc[i][j][x] = 0.f;

    const int nch = K >> 5;

#define LOAD_CHUNK(st, ch) do { \
    int kc = (ch) << 5; \
    size_t a0off = (size_t)(m0 + lr0) * K + kc + lc0; \
    size_t a1off = (size_t)(m0 + lr1) * K + kc + lc1; \
    size_t b0off = (size_t)(n0 + lr0) * K + kc + lc0; \
    size_t b1off = (size_t)(n0 + lr1) * K + kc + lc1; \
    uint32_t d0 = sb + TILE_OFF(st, 0) + (lr0 * TPAD + lc0) * 2; \
    uint32_t d1 = sb + TILE_OFF(st, 0) + (lr1 * TPAD + lc1) * 2; \
    CP16(d0, Ahi + a0off);            CP16(d1, Ahi + a1off); \
    CP16(d0 + TSZ, Alo + a0off);      CP16(d1 + TSZ, Alo + a1off); \
    CP16(d0 + 2 * TSZ, Bhi + b0off);  CP16(d1 + 2 * TSZ, Bhi + b1off); \
    CP16(d0 + 3 * TSZ, Blo + b0off);  CP16(d1 + 3 * TSZ, Blo + b1off); \
    CP_COMMIT(); \
} while (0)

    LOAD_CHUNK(0, 0);

    for (int ch = 0; ch < nch; ch++) {
        const int st = ch & 1;
        if (ch + 1 < nch) { LOAD_CHUNK(st ^ 1, ch + 1); CP_WAIT(1); }
        else              { CP_WAIT(0); }
        __syncthreads();

        const uint32_t sAh = sb + TILE_OFF(st, 0);
        const uint32_t sAl = sb + TILE_OFF(st, 1);
        const uint32_t sBh = sb + TILE_OFF(st, 2);
        const uint32_t sBl = sb + TILE_OFF(st, 3);

#pragma unroll
        for (int kh = 0; kh < 2; kh++) {
            const uint32_t col0 = (kh * 16 + 2 * tig) * 2;   // byte offset of k pair
            uint32_t ah[2][4], al[2][4], bh[8][2], bl[8][2];
#pragma unroll
            for (int mt = 0; mt < 2; mt++) {
                uint32_t r0 = (uint32_t)(wm * 32 + mt * 16 + g) * (TPAD * 2) + col0;
                uint32_t r1 = r0 + 8 * (TPAD * 2);
                ah[mt][0] = lds32(sAh + r0);      ah[mt][1] = lds32(sAh + r1);
                ah[mt][2] = lds32(sAh + r0 + 16); ah[mt][3] = lds32(sAh + r1 + 16);
                al[mt][0] = lds32(sAl + r0);      al[mt][1] = lds32(sAl + r1);
                al[mt][2] = lds32(sAl + r0 + 16); al[mt][3] = lds32(sAl + r1 + 16);
            }
#pragma unroll
            for (int nt = 0; nt < 8; nt++) {
                uint32_t rr = (uint32_t)(wn * 64 + nt * 8 + g) * (TPAD * 2) + col0;
                bh[nt][0] = lds32(sBh + rr); bh[nt][1] = lds32(sBh + rr + 16);
                bl[nt][0] = lds32(sBl + rr); bl[nt][1] = lds32(sBl + rr + 16);
            }
#pragma unroll
            for (int mt = 0; mt < 2; mt++)
#pragma unroll
                for (int nt = 0; nt < 8; nt++) MMA16816(acc[mt][nt], ah[mt], bh[nt]);
#pragma unroll
            for (int mt = 0; mt < 2; mt++)
#pragma unroll
                for (int nt = 0; nt < 8; nt++) MMA16816(acc[mt][nt], ah[mt], bl[nt]);
#pragma unroll
            for (int mt = 0; mt < 2; mt++)
#pragma unroll
                for (int nt = 0; nt < 8; nt++) MMA16816(acc[mt][nt], al[mt], bh[nt]);
        }
        __syncthreads();
    }

    // epilogue
    const float* sBias = (const float*)(smem + SM_BIAS);
#pragma unroll
    for (int mt = 0; mt < 2; mt++) {
        const int r0 = m0 + wm * 32 + mt * 16 + g;
        const int r1 = r0 + 8;
#pragma unroll
        for (int nt = 0; nt < 8; nt++) {
            const int cb = wn * 64 + nt * 8 + 2 * tig;      // block-local col
            const float b0v = sBias[cb], b1v = sBias[cb + 1];
            float v00 = acc[mt][nt][0] + b0v, v01 = acc[mt][nt][1] + b1v;
            float v10 = acc[mt][nt][2] + b0v, v11 = acc[mt][nt][3] + b1v;
            if (OUTMODE == 2) {
                __nv_bfloat162 h0, l0, h1, l1;
                h0.x = __float2bfloat16(v00); h0.y = __float2bfloat16(v01);
                l0.x = __float2bfloat16(v00 - __bfloat162float(h0.x));
                l0.y = __float2bfloat16(v01 - __bfloat162float(h0.y));
                h1.x = __float2bfloat16(v10); h1.y = __float2bfloat16(v11);
                l1.x = __float2bfloat16(v10 - __bfloat162float(h1.x));
                l1.y = __float2bfloat16(v11 - __bfloat162float(h1.y));
                size_t o0 = (size_t)r0 * ldc + n0 + cb;
                size_t o1 = (size_t)r1 * ldc + n0 + cb;
                *(__nv_bfloat162*)(Chi + o0) = h0;
                *(__nv_bfloat162*)(Clo + o0) = l0;
                *(__nv_bfloat162*)(Chi + o1) = h1;
                *(__nv_bfloat162*)(Clo + o1) = l1;
            } else {
                int row0 = (OUTMODE == 1) ? ((r0 & 63) * Tt + (r0 >> 6)) : r0;
                int row1 = (OUTMODE == 1) ? ((r1 & 63) * Tt + (r1 >> 6)) : r1;
                *(float2*)(C + (size_t)row0 * ldc + coloff + n0 + cb) = make_float2(v00, v01);
                *(float2*)(C + (size_t)row1 * ldc + coloff + n0 + cb) = make_float2(v10, v11);
            }
        }
    }
}

// ---------------- cluster-based bidirectional LSTM (unchanged, proven) ----------------
#define SW_FLOATS (256 * 33 * 4)
#define SH_FLOATS (2 * 2048)
#define LSTM_SMEM ((SW_FLOATS + SH_FLOATS) * 4)

#define CLUSTER_SYNC() do { \
    asm volatile("barrier.cluster.arrive.aligned;" ::: "memory"); \
    asm volatile("barrier.cluster.wait.aligned;"   ::: "memory"); \
} while (0)

__global__ void __launch_bounds__(256, 1) __cluster_dims__(8, 1, 1)
lstm_kernel(const float* __restrict__ xgf, const float* __restrict__ xgb,
            const float* __restrict__ Whhf, const float* __restrict__ Whhb,
            float* __restrict__ outp, int ldo, int coloff, int graphify)
{
    extern __shared__ float smemf[];
    float4* sW = (float4*)smemf;
    float*  sH = smemf + SW_FLOATS;

    const int tid = threadIdx.x;
    uint32_t rank;
    asm("mov.u32 %0, %%cluster_ctarank;" : "=r"(rank));
    const int dir  = blockIdx.x >> 6;
    const int bgrp = (blockIdx.x >> 3) & 7;
    const int b    = tid & 7;
    const int u    = tid >> 3;
    const int n    = (int)rank * 32 + u;
    const int bglob = bgrp * 8 + b;

    const float* xg  = dir ? xgb : xgf;
    const float* Whh = dir ? Whhb : Whhf;

#pragma unroll 4
    for (int it = 0; it < 32; it++) {
        int idx = it * 256 + tid;
        int uu  = (idx >> 3) & 31;
        int kk  = (idx & 7) | ((idx >> 8) << 3);
        int nn  = (int)rank * 32 + uu;
        float4 w;
        w.x = Whh[(size_t)(       nn) * HH + kk];
        w.y = Whh[(size_t)(HH   + nn) * HH + kk];
        w.z = Whh[(size_t)(2*HH + nn) * HH + kk];
        w.w = Whh[(size_t)(3*HH + nn) * HH + kk];
        sW[kk * 33 + uu] = w;
    }
    for (int i = tid; i < SH_FLOATS; i += 256) sH[i] = 0.f;

    const uint32_t sm_base = smem_u32(smemf);
    const uint32_t hslot   = sm_base + (uint32_t)(SW_FLOATS + n * 8 + b) * 4u;

    CLUSTER_SYNC();

    float c = 0.f;
    for (int step = 0; step < Tt; step++) {
        const int t    = dir ? (Tt - 1 - step) : step;
        const int rbuf = step & 1;
        const int wbuf = rbuf ^ 1;

        const float* xp = xg + ((size_t)t * Bb + bglob) * G4 + n;
        float xi = xp[0], xf = xp[HH], xgv = xp[2 * HH], xo = xp[3 * HH];

        const float*  hp = sH + rbuf * 2048 + b;
        const float4* wp = sW + u;

        unsigned long long accIF = 0ull, accGO = 0ull;
#pragma unroll 16
        for (int k = 0; k < HH; k++) {
            float h = hp[k * 8];
            longlong2 wv = *(const longlong2*)(wp + k * 33);
            unsigned hb = __float_as_uint(h);
            unsigned long long hh;
            asm("mov.b64 %0, {%1, %1};" : "=l"(hh) : "r"(hb));
            asm("fma.rn.f32x2 %0, %1, %2, %0;" : "+l"(accIF) : "l"(hh), "l"((unsigned long long)wv.x));
            asm("fma.rn.f32x2 %0, %1, %2, %0;" : "+l"(accGO) : "l"(hh), "l"((unsigned long long)wv.y));
        }
        unsigned ri, rf, rg, ro;
        asm("mov.b64 {%0, %1}, %2;" : "=r"(ri), "=r"(rf) : "l"(accIF));
        asm("mov.b64 {%0, %1}, %2;" : "=r"(rg), "=r"(ro) : "l"(accGO));

        float gi = __uint_as_float(ri) + xi;
        float gf = __uint_as_float(rf) + xf;
        float gg = __uint_as_float(rg) + xgv;
        float go = __uint_as_float(ro) + xo;
        float si = 1.f / (1.f + expf(-gi));
        float sf = 1.f / (1.f + expf(-gf));
        float so = 1.f / (1.f + expf(-go));
        c = sf * c + si * tanhf(gg);
        float h = so * tanhf(c);

        int row = graphify ? (bglob * Tt + t) : (t * Bb + bglob);
        outp[(size_t)row * ldo + coloff + dir * HH + n] = h;

        uint32_t dst = hslot + (uint32_t)(wbuf * 2048) * 4u;
#pragma unroll
        for (int r2 = 0; r2 < 8; r2++) {
            uint32_t ra;
            asm("mapa.shared::cluster.u32 %0, %1, %2;" : "=r"(ra) : "r"(dst), "r"(r2));
            asm volatile("st.shared::cluster.f32 [%0], %1;" :: "r"(ra), "f"(h));
        }
        CLUSTER_SYNC();
    }
}

// ---------------- launch ----------------
extern "C" void kernel_launch(void* const* d_in, const int* in_sizes, int n_in,
                              void* d_out, int out_size)
{
    const float* r1  = (const float*)d_in[0];
    const float* r2  = (const float*)d_in[1];
    const float* r3  = (const float*)d_in[2];
    const float* r4  = (const float*)d_in[3];
    const float* U_a = (const float*)d_in[4];
    const float* U_v = (const float*)d_in[5];
    const float* W_a = (const float*)d_in[7];
    const float* b_a = (const float*)d_in[8];
    const float* W_v = (const float*)d_in[9];
    const float* b_v = (const float*)d_in[10];
    const float* W_l = (const float*)d_in[11];
    const float* b_l = (const float*)d_in[12];
    const float* Wih0f = (const float*)d_in[13];
    const float* Whh0f = (const float*)d_in[14];
    const float* bih0f = (const float*)d_in[15];
    const float* bhh0f = (const float*)d_in[16];
    const float* Wih0b = (const float*)d_in[17];
    const float* Whh0b = (const float*)d_in[18];
    const float* bih0b = (const float*)d_in[19];
    const float* bhh0b = (const float*)d_in[20];
    const float* Wih1f = (const float*)d_in[21];
    const float* Whh1f = (const float*)d_in[22];
    const float* bih1f = (const float*)d_in[23];
    const float* bhh1f = (const float*)d_in[24];
    const float* Wih1b = (const float*)d_in[25];
    const float* Whh1b = (const float*)d_in[26];
    const float* bih1b = (const float*)d_in[27];
    const float* bhh1b = (const float*)d_in[28];
    float* out = (float*)d_out;

    float *pxf, *pxb, *ph0;
    cudaGetSymbolAddress((void**)&pxf, g_xgf);
    cudaGetSymbolAddress((void**)&pxb, g_xgb);
    cudaGetSymbolAddress((void**)&ph0, g_h0);
    __nv_bfloat16 *pUhi, *pUlo, *pUah, *pUal, *pUvh, *pUvl, *pXhi, *pXlo;
    __nv_bfloat16 *pWah, *pWal, *pWvh, *pWvl, *pWlh, *pWll;
    __nv_bfloat16 *pW0fh, *pW0fl, *pW0bh, *pW0bl, *pW1fh, *pW1fl, *pW1bh, *pW1bl;
    cudaGetSymbolAddress((void**)&pUhi, g_Uhi); cudaGetSymbolAddress((void**)&pUlo, g_Ulo);
    cudaGetSymbolAddress((void**)&pUah, g_Uah); cudaGetSymbolAddress((void**)&pUal, g_Ual);
    cudaGetSymbolAddress((void**)&pUvh, g_Uvh); cudaGetSymbolAddress((void**)&pUvl, g_Uvl);
    cudaGetSymbolAddress((void**)&pXhi, g_Xhi); cudaGetSymbolAddress((void**)&pXlo, g_Xlo);
    cudaGetSymbolAddress((void**)&pWah, g_Wah); cudaGetSymbolAddress((void**)&pWal, g_Wal);
    cudaGetSymbolAddress((void**)&pWvh, g_Wvh); cudaGetSymbolAddress((void**)&pWvl, g_Wvl);
    cudaGetSymbolAddress((void**)&pWlh, g_Wlh); cudaGetSymbolAddress((void**)&pWll, g_Wll);
    cudaGetSymbolAddress((void**)&pW0fh, g_W0fh); cudaGetSymbolAddress((void**)&pW0fl, g_W0fl);
    cudaGetSymbolAddress((void**)&pW0bh, g_W0bh); cudaGetSymbolAddress((void**)&pW0bl, g_W0bl);
    cudaGetSymbolAddress((void**)&pW1fh, g_W1fh); cudaGetSymbolAddress((void**)&pW1fl, g_W1fl);
    cudaGetSymbolAddress((void**)&pW1bh, g_W1bh); cudaGetSymbolAddress((void**)&pW1bl, g_W1bl);

    cudaFuncSetAttribute(gemm_mma<0>, cudaFuncAttributeMaxDynamicSharedMemorySize, GEMM_SMEM);
    cudaFuncSetAttribute(gemm_mma<1>, cudaFuncAttributeMaxDynamicSharedMemorySize, GEMM_SMEM);
    cudaFuncSetAttribute(gemm_mma<2>, cudaFuncAttributeMaxDynamicSharedMemorySize, GEMM_SMEM);
    cudaFuncSetAttribute(lstm_kernel, cudaFuncAttributeMaxDynamicSharedMemorySize, LSTM_SMEM);

    // LN2 stats + fused U (bf16 split)
    stats_kernel<<<256, 256>>>(r1, r2, r3, r4);
    build_u_split<<<TB * DM / 4 / 256, 256>>>(r1, r2, r3, r4);

    // conversions
    convert_pad<<<(TB * 128 + 255) / 256, 256>>>(U_a, pUah, pUal, 100, 128, TB * 128);
    convert_pad<<<(DG * 128 + 255) / 256, 256>>>(W_a, pWah, pWal, 100, 128, DG * 128);
    convert_pad<<<(TB * DG + 255) / 256, 256>>>(U_v, pUvh, pUvl, DG, DG, TB * DG);
    convert_pad<<<(DG * DG + 255) / 256, 256>>>(W_v, pWvh, pWvl, DG, DG, DG * DG);
    convert_pad<<<(DG * DM + 255) / 256, 256>>>(W_l, pWlh, pWll, DM, DM, DG * DM);
    convert_pad<<<(G4 * DG + 255) / 256, 256>>>(Wih0f, pW0fh, pW0fl, DG, DG, G4 * DG);
    convert_pad<<<(G4 * DG + 255) / 256, 256>>>(Wih0b, pW0bh, pW0bl, DG, DG, G4 * DG);
    convert_pad<<<(G4 * DG + 255) / 256, 256>>>(Wih1f, pW1fh, pW1fl, DG, DG, G4 * DG);
    convert_pad<<<(G4 * DG + 255) / 256, 256>>>(Wih1b, pW1bh, pW1bl, DG, DG, G4 * DG);

    dim3 g512(4, 48), g1024(8, 48);

    // emotions_a / emotions_v -> out (graphify fused)
    gemm_mma<1><<<g512, 256, GEMM_SMEM>>>(pUah, pUal, pWah, pWal, b_a, nullptr,
                                          out, nullptr, nullptr, 128, 1536, 0);
    gemm_mma<1><<<g512, 256, GEMM_SMEM>>>(pUvh, pUvl, pWvh, pWvl, b_v, nullptr,
                                          out, nullptr, nullptr, 512, 1536, 512);
    // Ul = U @ W_l^T + b_l  -> bf16 pair (g_Xhi/g_Xlo)
    gemm_mma<2><<<g512, 256, GEMM_SMEM>>>(pUhi, pUlo, pWlh, pWll, b_l, nullptr,
                                          nullptr, pXhi, pXlo, 1024, 512, 0);
    // LSTM layer 0 input gates
    gemm_mma<0><<<g1024, 256, GEMM_SMEM>>>(pXhi, pXlo, pW0fh, pW0fl, bih0f, bhh0f,
                                           pxf, nullptr, nullptr, 512, 1024, 0);
    gemm_mma<0><<<g1024, 256, GEMM_SMEM>>>(pXhi, pXlo, pW0bh, pW0bl, bih0b, bhh0b,
                                           pxb, nullptr, nullptr, 512, 1024, 0);
    lstm_kernel<<<128, 256, LSTM_SMEM>>>(pxf, pxb, Whh0f, Whh0b, ph0, 512, 0, 0);

    // h0 -> bf16 pair (reuse g_Xhi/g_Xlo)
    convert_pad<<<(TB * DG + 255) / 256, 256>>>(ph0, pXhi, pXlo, DG, DG, TB * DG);

    // LSTM layer 1
    gemm_mma<0><<<g1024, 256, GEMM_SMEM>>>(pXhi, pXlo, pW1fh, pW1fl, bih1f, bhh1f,
                                           pxf, nullptr, nullptr, 512, 1024, 0);
    gemm_mma<0><<<g1024, 256, GEMM_SMEM>>>(pXhi, pXlo, pW1bh, pW1bl, bih1b, bhh1b,
                                           pxb, nullptr, nullptr, 512, 1024, 0);
    lstm_kernel<<<128, 256, LSTM_SMEM>>>(pxf, pxb, Whh1f, Whh1b, out, 1536, 1024, 1);
}

// round 5
// speedup vs baseline: 1.6458x; 1.0049x over previous
#include <cuda_runtime.h>
#include <cuda_bf16.h>
#include <math.h>
#include <stdint.h>

// ---------------- problem constants ----------------
#define Tt   96
#define Bb   64
#define TB   6144      // Tt*Bb
#define DM   1024
#define DG   512
#define HH   256
#define G4   1024      // 4*HH

// ---------------- scratch ----------------
__device__ float g_xgf[TB * G4];      // transposed layout [t][col][b]
__device__ float g_xgb[TB * G4];
__device__ float g_alpha[4 * Bb];
__device__ float g_shift[4 * Bb];

__device__ __nv_bfloat16 g_Uhi[TB * DM],  g_Ulo[TB * DM];
__device__ __nv_bfloat16 g_Uah[TB * 128], g_Ual[TB * 128];
__device__ __nv_bfloat16 g_Uvh[TB * DG],  g_Uvl[TB * DG];
__device__ __nv_bfloat16 g_Xhi[TB * DG],  g_Xlo[TB * DG];    // Ul pair
__device__ __nv_bfloat16 g_Yhi[TB * DG],  g_Ylo[TB * DG];    // h0 pair (lstm0 out)
__device__ __nv_bfloat16 g_Wah[DG * 128], g_Wal[DG * 128];
__device__ __nv_bfloat16 g_Wvh[DG * DG],  g_Wvl[DG * DG];
__device__ __nv_bfloat16 g_Wlh[DG * DM],  g_Wll[DG * DM];
__device__ __nv_bfloat16 g_W0fh[G4 * DG], g_W0fl[G4 * DG];
__device__ __nv_bfloat16 g_W0bh[G4 * DG], g_W0bl[G4 * DG];
__device__ __nv_bfloat16 g_W1fh[G4 * DG], g_W1fl[G4 * DG];
__device__ __nv_bfloat16 g_W1bh[G4 * DG], g_W1bl[G4 * DG];

// ---------------- helpers ----------------
__device__ __forceinline__ uint32_t smem_u32(const void* p) {
    uint32_t a;
    asm("{ .reg .u64 t; cvta.to.shared.u64 t, %1; cvt.u32.u64 %0, t; }" : "=r"(a) : "l"(p));
    return a;
}
__device__ __forceinline__ uint32_t lds32(uint32_t addr) {
    uint32_t v;
    asm volatile("ld.shared.b32 %0, [%1];" : "=r"(v) : "r"(addr));
    return v;
}
#define CP16(dst, src) \
    asm volatile("cp.async.cg.shared.global [%0], [%1], 16;" :: "r"(dst), "l"(src))
#define CP_COMMIT() asm volatile("cp.async.commit_group;" ::: "memory")
#define CP_WAIT(n)  asm volatile("cp.async.wait_group %0;" :: "n"(n) : "memory")

#define MMA16816(d, a, b) \
    asm volatile("mma.sync.aligned.m16n8k16.row.col.f32.bf16.bf16.f32 " \
        "{%0,%1,%2,%3}, {%4,%5,%6,%7}, {%8,%9}, {%0,%1,%2,%3};" \
        : "+f"((d)[0]), "+f"((d)[1]), "+f"((d)[2]), "+f"((d)[3]) \
        : "r"((a)[0]), "r"((a)[1]), "r"((a)[2]), "r"((a)[3]), "r"((b)[0]), "r"((b)[1]))

// ---------------- LN2 statistics ----------------
__global__ void stats_kernel(const float* __restrict__ r1, const float* __restrict__ r2,
                             const float* __restrict__ r3, const float* __restrict__ r4)
{
    int i = blockIdx.x >> 6;
    int b = blockIdx.x & 63;
    const float* r = (i == 0) ? r1 : (i == 1) ? r2 : (i == 2) ? r3 : r4;
    float s = 0.f, q = 0.f;
    const float4* base = (const float4*)(r + (size_t)b * DM);
    for (int t = 0; t < Tt; t++) {
        float4 v = base[(size_t)t * (Bb * DM / 4) + threadIdx.x];
        s += v.x + v.y + v.z + v.w;
        q += v.x * v.x + v.y * v.y + v.z * v.z + v.w * v.w;
    }
    __shared__ float ss[256], sq[256];
    ss[threadIdx.x] = s; sq[threadIdx.x] = q;
    __syncthreads();
    for (int st = 128; st > 0; st >>= 1) {
        if (threadIdx.x < st) { ss[threadIdx.x] += ss[threadIdx.x + st]; sq[threadIdx.x] += sq[threadIdx.x + st]; }
        __syncthreads();
    }
    if (threadIdx.x == 0) {
        const float inv_n = 1.f / (float)(Tt * DM);
        float m   = ss[0] * inv_n;
        float var = sq[0] * inv_n - m * m;
        float a   = 0.25f * rsqrtf(var + 1e-5f);
        g_alpha[i * Bb + b] = a;
        g_shift[i * Bb + b] = a * m;
    }
}

// ---------------- fused U build + bf16 split ----------------
__global__ void build_u_split(const float* __restrict__ r1, const float* __restrict__ r2,
                              const float* __restrict__ r3, const float* __restrict__ r4)
{
    size_t idx = (size_t)blockIdx.x * blockDim.x + threadIdx.x;
    size_t e   = idx * 4;
    int b = (int)((e >> 10) & 63);
    float a1 = g_alpha[b], a2 = g_alpha[64 + b], a3 = g_alpha[128 + b], a4 = g_alpha[192 + b];
    float sh = g_shift[b] + g_shift[64 + b] + g_shift[128 + b] + g_shift[192 + b];
    float4 v1 = ((const float4*)r1)[idx];
    float4 v2 = ((const float4*)r2)[idx];
    float4 v3 = ((const float4*)r3)[idx];
    float4 v4 = ((const float4*)r4)[idx];
    float o[4];
    o[0] = a1 * v1.x + a2 * v2.x + a3 * v3.x + a4 * v4.x - sh;
    o[1] = a1 * v1.y + a2 * v2.y + a3 * v3.y + a4 * v4.y - sh;
    o[2] = a1 * v1.z + a2 * v2.z + a3 * v3.z + a4 * v4.z - sh;
    o[3] = a1 * v1.w + a2 * v2.w + a3 * v3.w + a4 * v4.w - sh;
    __nv_bfloat162 hi0, hi1, lo0, lo1;
    hi0.x = __float2bfloat16(o[0]); hi0.y = __float2bfloat16(o[1]);
    hi1.x = __float2bfloat16(o[2]); hi1.y = __float2bfloat16(o[3]);
    lo0.x = __float2bfloat16(o[0] - __bfloat162float(hi0.x));
    lo0.y = __float2bfloat16(o[1] - __bfloat162float(hi0.y));
    lo1.x = __float2bfloat16(o[2] - __bfloat162float(hi1.x));
    lo1.y = __float2bfloat16(o[3] - __bfloat162float(hi1.y));
    ((__nv_bfloat162*)g_Uhi)[idx * 2]     = hi0;
    ((__nv_bfloat162*)g_Uhi)[idx * 2 + 1] = hi1;
    ((__nv_bfloat162*)g_Ulo)[idx * 2]     = lo0;
    ((__nv_bfloat162*)g_Ulo)[idx * 2 + 1] = lo1;
}

// ---------------- batched fp32 -> bf16 hi/lo ----------------
struct CJobs {
    const float*   in[7];
    __nv_bfloat16* hi[7];
    __nv_bfloat16* lo[7];
    int K[7], Kpad[7], total[7];
};
__global__ void convert_batch(CJobs j)
{
    int job = blockIdx.y;
    int idx = blockIdx.x * 256 + threadIdx.x;
    if (idx >= j.total[job]) return;
    int K = j.K[job], Kp = j.Kpad[job];
    int r = idx / Kp, c = idx - r * Kp;
    float v = (c < K) ? j.in[job][(size_t)r * K + c] : 0.f;
    __nv_bfloat16 h = __float2bfloat16(v);
    j.hi[job][idx] = h;
    j.lo[job][idx] = __float2bfloat16(v - __bfloat162float(h));
}

// ---------------- bf16-split GEMM via mma.sync ----------------
// OUTMODE: 1 = fp32 C with graphify row remap, 2 = bf16 hi/lo pair.
#define TPAD  40
#define TSZ   (128 * TPAD * 2)
#define SM_BIAS 0
#define SM_TILES 512
#define TILE_OFF(st, mat) (SM_TILES + ((st) * 4 + (mat)) * TSZ)
#define GEMM_SMEM (SM_TILES + 8 * TSZ)

#define GEMM_PROLOG() \
    extern __shared__ char smem[]; \
    const uint32_t sb = smem_u32(smem); \
    const int tid  = threadIdx.x; \
    const int lane = tid & 31, wid = tid >> 5; \
    const int wm = wid >> 1, wn = wid & 1; \
    const int g = lane >> 2, tig = lane & 3; \
    const int n0 = blockIdx.x * 128, m0 = blockIdx.y * 128; \
    const int lr0 = (tid * 2) >> 2,     lc0 = ((tid * 2) & 3) * 8; \
    const int lr1 = (tid * 2 + 1) >> 2, lc1 = ((tid * 2 + 1) & 3) * 8; \
    float acc[2][8][4]; \
    _Pragma("unroll") for (int i = 0; i < 2; i++) \
    _Pragma("unroll") for (int jj = 0; jj < 8; jj++) \
    _Pragma("unroll") for (int x = 0; x < 4; x++) acc[i][jj][x] = 0.f;

#define LOAD_CHUNK(st, ch) do { \
    int kc = (ch) << 5; \
    size_t a0off = (size_t)(m0 + lr0) * K + kc + lc0; \
    size_t a1off = (size_t)(m0 + lr1) * K + kc + lc1; \
    size_t b0off = (size_t)(n0 + lr0) * K + kc + lc0; \
    size_t b1off = (size_t)(n0 + lr1) * K + kc + lc1; \
    uint32_t d0 = sb + TILE_OFF(st, 0) + (lr0 * TPAD + lc0) * 2; \
    uint32_t d1 = sb + TILE_OFF(st, 0) + (lr1 * TPAD + lc1) * 2; \
    CP16(d0, Ahi + a0off);            CP16(d1, Ahi + a1off); \
    CP16(d0 + TSZ, Alo + a0off);      CP16(d1 + TSZ, Alo + a1off); \
    CP16(d0 + 2 * TSZ, Bhi + b0off);  CP16(d1 + 2 * TSZ, Bhi + b1off); \
    CP16(d0 + 3 * TSZ, Blo + b0off);  CP16(d1 + 3 * TSZ, Blo + b1off); \
    CP_COMMIT(); \
} while (0)

#define GEMM_MAINLOOP() \
    const int nch = K >> 5; \
    LOAD_CHUNK(0, 0); \
    for (int ch = 0; ch < nch; ch++) { \
        const int st = ch & 1; \
        if (ch + 1 < nch) { LOAD_CHUNK(st ^ 1, ch + 1); CP_WAIT(1); } \
        else              { CP_WAIT(0); } \
        __syncthreads(); \
        const uint32_t sAh = sb + TILE_OFF(st, 0); \
        const uint32_t sAl = sb + TILE_OFF(st, 1); \
        const uint32_t sBh = sb + TILE_OFF(st, 2); \
        const uint32_t sBl = sb + TILE_OFF(st, 3); \
        _Pragma("unroll") \
        for (int kh = 0; kh < 2; kh++) { \
            const uint32_t col0 = (kh * 16 + 2 * tig) * 2; \
            uint32_t ah[2][4], al[2][4], bh[8][2], bl[8][2]; \
            _Pragma("unroll") \
            for (int mt = 0; mt < 2; mt++) { \
                uint32_t r0a = (uint32_t)(wm * 32 + mt * 16 + g) * (TPAD * 2) + col0; \
                uint32_t r1a = r0a + 8 * (TPAD * 2); \
                ah[mt][0] = lds32(sAh + r0a);      ah[mt][1] = lds32(sAh + r1a); \
                ah[mt][2] = lds32(sAh + r0a + 16); ah[mt][3] = lds32(sAh + r1a + 16); \
                al[mt][0] = lds32(sAl + r0a);      al[mt][1] = lds32(sAl + r1a); \
                al[mt][2] = lds32(sAl + r0a + 16); al[mt][3] = lds32(sAl + r1a + 16); \
            } \
            _Pragma("unroll") \
            for (int nt = 0; nt < 8; nt++) { \
                uint32_t rr = (uint32_t)(wn * 64 + nt * 8 + g) * (TPAD * 2) + col0; \
                bh[nt][0] = lds32(sBh + rr); bh[nt][1] = lds32(sBh + rr + 16); \
                bl[nt][0] = lds32(sBl + rr); bl[nt][1] = lds32(sBl + rr + 16); \
            } \
            _Pragma("unroll") \
            for (int mt = 0; mt < 2; mt++) \
            _Pragma("unroll") \
                for (int nt = 0; nt < 8; nt++) MMA16816(acc[mt][nt], ah[mt], bh[nt]); \
            _Pragma("unroll") \
            for (int mt = 0; mt < 2; mt++) \
            _Pragma("unroll") \
                for (int nt = 0; nt < 8; nt++) MMA16816(acc[mt][nt], ah[mt], bl[nt]); \
            _Pragma("unroll") \
            for (int mt = 0; mt < 2; mt++) \
            _Pragma("unroll") \
                for (int nt = 0; nt < 8; nt++) MMA16816(acc[mt][nt], al[mt], bh[nt]); \
        } \
        __syncthreads(); \
    }

template <int OUTMODE>
__global__ void __launch_bounds__(256, 1) gemm_mma(
    const __nv_bfloat16* __restrict__ Ahi, const __nv_bfloat16* __restrict__ Alo,
    const __nv_bfloat16* __restrict__ Bhi, const __nv_bfloat16* __restrict__ Blo,
    const float* __restrict__ bias1, const float* __restrict__ bias2,
    float* __restrict__ C, __nv_bfloat16* __restrict__ Chi, __nv_bfloat16* __restrict__ Clo,
    int K, int ldc, int coloff)
{
    GEMM_PROLOG();
    if (tid < 128) {
        float bv = bias1[n0 + tid];
        if (bias2) bv += bias2[n0 + tid];
        *(float*)(smem + SM_BIAS + tid * 4) = bv;
    }
    GEMM_MAINLOOP();

    const float* sBias = (const float*)(smem + SM_BIAS);
#pragma unroll
    for (int mt = 0; mt < 2; mt++) {
        const int r0 = m0 + wm * 32 + mt * 16 + g;
        const int r1 = r0 + 8;
#pragma unroll
        for (int nt = 0; nt < 8; nt++) {
            const int cb = wn * 64 + nt * 8 + 2 * tig;
            const float b0v = sBias[cb], b1v = sBias[cb + 1];
            float v00 = acc[mt][nt][0] + b0v, v01 = acc[mt][nt][1] + b1v;
            float v10 = acc[mt][nt][2] + b0v, v11 = acc[mt][nt][3] + b1v;
            if (OUTMODE == 2) {
                __nv_bfloat162 h0, l0, h1, l1;
                h0.x = __float2bfloat16(v00); h0.y = __float2bfloat16(v01);
                l0.x = __float2bfloat16(v00 - __bfloat162float(h0.x));
                l0.y = __float2bfloat16(v01 - __bfloat162float(h0.y));
                h1.x = __float2bfloat16(v10); h1.y = __float2bfloat16(v11);
                l1.x = __float2bfloat16(v10 - __bfloat162float(h1.x));
                l1.y = __float2bfloat16(v11 - __bfloat162float(h1.y));
                size_t o0 = (size_t)r0 * ldc + n0 + cb;
                size_t o1 = (size_t)r1 * ldc + n0 + cb;
                *(__nv_bfloat162*)(Chi + o0) = h0;
                *(__nv_bfloat162*)(Clo + o0) = l0;
                *(__nv_bfloat162*)(Chi + o1) = h1;
                *(__nv_bfloat162*)(Clo + o1) = l1;
            } else {
                int row0 = (r0 & 63) * Tt + (r0 >> 6);
                int row1 = (r1 & 63) * Tt + (r1 >> 6);
                *(float2*)(C + (size_t)row0 * ldc + coloff + n0 + cb) = make_float2(v00, v01);
                *(float2*)(C + (size_t)row1 * ldc + coloff + n0 + cb) = make_float2(v10, v11);
            }
        }
    }
}

// xg GEMM: blockIdx.z selects forward/backward; output in transposed layout [t][col][b]
__global__ void __launch_bounds__(256, 1) gemm_xg(
    const __nv_bfloat16* __restrict__ Ahi, const __nv_bfloat16* __restrict__ Alo,
    const __nv_bfloat16* __restrict__ Bfh, const __nv_bfloat16* __restrict__ Bfl,
    const __nv_bfloat16* __restrict__ Bbh, const __nv_bfloat16* __restrict__ Bbl,
    const float* __restrict__ bf1, const float* __restrict__ bf2,
    const float* __restrict__ bb1, const float* __restrict__ bb2,
    float* __restrict__ Cf, float* __restrict__ Cb, int K)
{
    const __nv_bfloat16* Bhi = blockIdx.z ? Bbh : Bfh;
    const __nv_bfloat16* Blo = blockIdx.z ? Bbl : Bfl;
    const float* bias1 = blockIdx.z ? bb1 : bf1;
    const float* bias2 = blockIdx.z ? bb2 : bf2;
    float* C = blockIdx.z ? Cb : Cf;

    GEMM_PROLOG();
    if (tid < 128)
        *(float*)(smem + SM_BIAS + tid * 4) = bias1[n0 + tid] + bias2[n0 + tid];
    GEMM_MAINLOOP();

    const float* sBias = (const float*)(smem + SM_BIAS);
#pragma unroll
    for (int mt = 0; mt < 2; mt++) {
        const int r0 = m0 + wm * 32 + mt * 16 + g;
        const int r1 = r0 + 8;
        const int t0 = r0 >> 6, b0r = r0 & 63;
        const int t1 = r1 >> 6, b1r = r1 & 63;
#pragma unroll
        for (int nt = 0; nt < 8; nt++) {
            const int cb = wn * 64 + nt * 8 + 2 * tig;
            const float b0v = sBias[cb], b1v = sBias[cb + 1];
            float* p0 = C + (size_t)t0 * (Bb * G4) + (size_t)(n0 + cb) * Bb;
            float* p1 = C + (size_t)t1 * (Bb * G4) + (size_t)(n0 + cb) * Bb;
            p0[b0r]      = acc[mt][nt][0] + b0v;
            p0[Bb + b0r] = acc[mt][nt][1] + b1v;
            p1[b1r]      = acc[mt][nt][2] + b0v;
            p1[Bb + b1r] = acc[mt][nt][3] + b1v;
        }
    }
}

// ---------------- cluster-based bidirectional LSTM ----------------
#define SW_FLOATS (256 * 33 * 4)
#define SH_FLOATS (2 * 2048)
#define LSTM_SMEM ((SW_FLOATS + SH_FLOATS) * 4)

#define CLUSTER_SYNC() do { \
    asm volatile("barrier.cluster.arrive.aligned;" ::: "memory"); \
    asm volatile("barrier.cluster.wait.aligned;"   ::: "memory"); \
} while (0)

// MODE 0: write bf16 hi/lo pair (layer-0 output, row-major [t*64+b][dir*256+n])
// MODE 1: write fp32 graphified into d_out cols [1024,1536)
__global__ void __launch_bounds__(256, 1) __cluster_dims__(8, 1, 1)
lstm_kernel(const float* __restrict__ xgf, const float* __restrict__ xgb,
            const float* __restrict__ Whhf, const float* __restrict__ Whhb,
            float* __restrict__ outp,
            __nv_bfloat16* __restrict__ Chi, __nv_bfloat16* __restrict__ Clo,
            int mode)
{
    extern __shared__ float smemf[];
    float4* sW = (float4*)smemf;
    float*  sH = smemf + SW_FLOATS;

    const int tid  = threadIdx.x;
    const int lane = tid & 31;
    uint32_t rank;
    asm("mov.u32 %0, %%cluster_ctarank;" : "=r"(rank));
    const int dir  = blockIdx.x >> 6;
    const int bgrp = (blockIdx.x >> 3) & 7;
    const int b    = tid & 7;
    const int u    = tid >> 3;
    const int n    = (int)rank * 32 + u;
    const int bglob = bgrp * 8 + b;

    const float* xg  = dir ? xgb : xgf;
    const float* Whh = dir ? Whhb : Whhf;

#pragma unroll 4
    for (int it = 0; it < 32; it++) {
        int idx = it * 256 + tid;
        int uu  = (idx >> 3) & 31;
        int kk  = (idx & 7) | ((idx >> 8) << 3);
        int nn  = (int)rank * 32 + uu;
        float4 w;
        w.x = Whh[(size_t)(       nn) * HH + kk];
        w.y = Whh[(size_t)(HH   + nn) * HH + kk];
        w.z = Whh[(size_t)(2*HH + nn) * HH + kk];
        w.w = Whh[(size_t)(3*HH + nn) * HH + kk];
        sW[kk * 33 + uu] = w;
    }
    for (int i = tid; i < SH_FLOATS; i += 256) sH[i] = 0.f;

    const uint32_t sm_base = smem_u32(smemf);

    CLUSTER_SYNC();

    float c = 0.f;
    for (int step = 0; step < Tt; step++) {
        const int t    = dir ? (Tt - 1 - step) : step;
        const int rbuf = step & 1;
        const int wbuf = rbuf ^ 1;

        // coalesced x-gate loads from transposed layout [t][col][b]
        const float* xp = xg + (size_t)t * (Bb * G4) + (size_t)n * Bb + bglob;
        float xi  = xp[0];
        float xf  = xp[HH * Bb];
        float xgv = xp[2 * HH * Bb];
        float xo  = xp[3 * HH * Bb];

        const float*  hp = sH + rbuf * 2048 + b;
        const float4* wp = sW + u;

        unsigned long long accIF = 0ull, accGO = 0ull;
#pragma unroll 16
        for (int k = 0; k < HH; k++) {
            float h = hp[k * 8];
            longlong2 wv = *(const longlong2*)(wp + k * 33);
            unsigned hb = __float_as_uint(h);
            unsigned long long hh;
            asm("mov.b64 %0, {%1, %1};" : "=l"(hh) : "r"(hb));
            asm("fma.rn.f32x2 %0, %1, %2, %0;" : "+l"(accIF) : "l"(hh), "l"((unsigned long long)wv.x));
            asm("fma.rn.f32x2 %0, %1, %2, %0;" : "+l"(accGO) : "l"(hh), "l"((unsigned long long)wv.y));
        }
        unsigned ri, rf, rg, ro;
        asm("mov.b64 {%0, %1}, %2;" : "=r"(ri), "=r"(rf) : "l"(accIF));
        asm("mov.b64 {%0, %1}, %2;" : "=r"(rg), "=r"(ro) : "l"(accGO));

        float gi = __uint_as_float(ri) + xi;
        float gf = __uint_as_float(rf) + xf;
        float gg = __uint_as_float(rg) + xgv;
        float go = __uint_as_float(ro) + xo;
        float si = 1.f / (1.f + expf(-gi));
        float sf = 1.f / (1.f + expf(-gf));
        float so = 1.f / (1.f + expf(-go));
        c = sf * c + si * tanhf(gg);
        float h = so * tanhf(c);

        // output
        if (mode == 0) {
            size_t o = ((size_t)t * Bb + bglob) * DG + dir * HH + n;
            __nv_bfloat16 hh16 = __float2bfloat16(h);
            Chi[o] = hh16;
            Clo[o] = __float2bfloat16(h - __bfloat162float(hh16));
        } else {
            int row = bglob * Tt + t;
            outp[(size_t)row * 1536 + 1024 + dir * HH + n] = h;
        }

        // pack 4 b-values into float4 via shuffles, then 8 DSMEM v4 stores
        float4 p;
        int lb = lane & ~3;
        p.x = __shfl_sync(0xffffffffu, h, lb);
        p.y = __shfl_sync(0xffffffffu, h, lb + 1);
        p.z = __shfl_sync(0xffffffffu, h, lb + 2);
        p.w = __shfl_sync(0xffffffffu, h, lb + 3);
        if ((b & 3) == 0) {
            uint32_t dst = sm_base + (uint32_t)(SW_FLOATS + wbuf * 2048 + n * 8 + b) * 4u;
#pragma unroll
            for (int r2 = 0; r2 < 8; r2++) {
                uint32_t ra;
                asm("mapa.shared::cluster.u32 %0, %1, %2;" : "=r"(ra) : "r"(dst), "r"(r2));
                asm volatile("st.shared::cluster.v4.f32 [%0], {%1, %2, %3, %4};"
                             :: "r"(ra), "f"(p.x), "f"(p.y), "f"(p.z), "f"(p.w));
            }
        }
        CLUSTER_SYNC();
    }
}

// ---------------- launch ----------------
extern "C" void kernel_launch(void* const* d_in, const int* in_sizes, int n_in,
                              void* d_out, int out_size)
{
    const float* r1  = (const float*)d_in[0];
    const float* r2  = (const float*)d_in[1];
    const float* r3  = (const float*)d_in[2];
    const float* r4  = (const float*)d_in[3];
    const float* U_a = (const float*)d_in[4];
    const float* U_v = (const float*)d_in[5];
    const float* W_a = (const float*)d_in[7];
    const float* b_a = (const float*)d_in[8];
    const float* W_v = (const float*)d_in[9];
    const float* b_v = (const float*)d_in[10];
    const float* W_l = (const float*)d_in[11];
    const float* b_l = (const float*)d_in[12];
    const float* Wih0f = (const float*)d_in[13];
    const float* Whh0f = (const float*)d_in[14];
    const float* bih0f = (const float*)d_in[15];
    const float* bhh0f = (const float*)d_in[16];
    const float* Wih0b = (const float*)d_in[17];
    const float* Whh0b = (const float*)d_in[18];
    const float* bih0b = (const float*)d_in[19];
    const float* bhh0b = (const float*)d_in[20];
    const float* Wih1f = (const float*)d_in[21];
    const float* Whh1f = (const float*)d_in[22];
    const float* bih1f = (const float*)d_in[23];
    const float* bhh1f = (const float*)d_in[24];
    const float* Wih1b = (const float*)d_in[25];
    const float* Whh1b = (const float*)d_in[26];
    const float* bih1b = (const float*)d_in[27];
    const float* bhh1b = (const float*)d_in[28];
    float* out = (float*)d_out;

    float *pxf, *pxb;
    cudaGetSymbolAddress((void**)&pxf, g_xgf);
    cudaGetSymbolAddress((void**)&pxb, g_xgb);
    __nv_bfloat16 *pUhi, *pUlo, *pUah, *pUal, *pUvh, *pUvl, *pXhi, *pXlo, *pYhi, *pYlo;
    __nv_bfloat16 *pWah, *pWal, *pWvh, *pWvl, *pWlh, *pWll;
    __nv_bfloat16 *pW0fh, *pW0fl, *pW0bh, *pW0bl, *pW1fh, *pW1fl, *pW1bh, *pW1bl;
    cudaGetSymbolAddress((void**)&pUhi, g_Uhi); cudaGetSymbolAddress((void**)&pUlo, g_Ulo);
    cudaGetSymbolAddress((void**)&pUah, g_Uah); cudaGetSymbolAddress((void**)&pUal, g_Ual);
    cudaGetSymbolAddress((void**)&pUvh, g_Uvh); cudaGetSymbolAddress((void**)&pUvl, g_Uvl);
    cudaGetSymbolAddress((void**)&pXhi, g_Xhi); cudaGetSymbolAddress((void**)&pXlo, g_Xlo);
    cudaGetSymbolAddress((void**)&pYhi, g_Yhi); cudaGetSymbolAddress((void**)&pYlo, g_Ylo);
    cudaGetSymbolAddress((void**)&pWah, g_Wah); cudaGetSymbolAddress((void**)&pWal, g_Wal);
    cudaGetSymbolAddress((void**)&pWvh, g_Wvh); cudaGetSymbolAddress((void**)&pWvl, g_Wvl);
    cudaGetSymbolAddress((void**)&pWlh, g_Wlh); cudaGetSymbolAddress((void**)&pWll, g_Wll);
    cudaGetSymbolAddress((void**)&pW0fh, g_W0fh); cudaGetSymbolAddress((void**)&pW0fl, g_W0fl);
    cudaGetSymbolAddress((void**)&pW0bh, g_W0bh); cudaGetSymbolAddress((void**)&pW0bl, g_W0bl);
    cudaGetSymbolAddress((void**)&pW1fh, g_W1fh); cudaGetSymbolAddress((void**)&pW1fl, g_W1fl);
    cudaGetSymbolAddress((void**)&pW1bh, g_W1bh); cudaGetSymbolAddress((void**)&pW1bl, g_W1bl);

    cudaFuncSetAttribute(gemm_mma<1>, cudaFuncAttributeMaxDynamicSharedMemorySize, GEMM_SMEM);
    cudaFuncSetAttribute(gemm_mma<2>, cudaFuncAttributeMaxDynamicSharedMemorySize, GEMM_SMEM);
    cudaFuncSetAttribute(gemm_xg,     cudaFuncAttributeMaxDynamicSharedMemorySize, GEMM_SMEM);
    cudaFuncSetAttribute(lstm_kernel, cudaFuncAttributeMaxDynamicSharedMemorySize, LSTM_SMEM);

    // 1-2: LN2 stats + fused U (bf16 split)
    stats_kernel<<<256, 256>>>(r1, r2, r3, r4);
    build_u_split<<<TB * DM / 4 / 256, 256>>>(r1, r2, r3, r4);

    // 3: all weight conversions (7 jobs)
    CJobs wj;
    wj.in[0] = W_l;   wj.hi[0] = pWlh;  wj.lo[0] = pWll;  wj.K[0] = DM;  wj.Kpad[0] = DM;  wj.total[0] = DG * DM;
    wj.in[1] = Wih0f; wj.hi[1] = pW0fh; wj.lo[1] = pW0fl; wj.K[1] = DG;  wj.Kpad[1] = DG;  wj.total[1] = G4 * DG;
    wj.in[2] = Wih0b; wj.hi[2] = pW0bh; wj.lo[2] = pW0bl; wj.K[2] = DG;  wj.Kpad[2] = DG;  wj.total[2] = G4 * DG;
    wj.in[3] = Wih1f; wj.hi[3] = pW1fh; wj.lo[3] = pW1fl; wj.K[3] = DG;  wj.Kpad[3] = DG;  wj.total[3] = G4 * DG;
    wj.in[4] = Wih1b; wj.hi[4] = pW1bh; wj.lo[4] = pW1bl; wj.K[4] = DG;  wj.Kpad[4] = DG;  wj.total[4] = G4 * DG;
    wj.in[5] = W_a;   wj.hi[5] = pWah;  wj.lo[5] = pWal;  wj.K[5] = 100; wj.Kpad[5] = 128; wj.total[5] = DG * 128;
    wj.in[6] = W_v;   wj.hi[6] = pWvh;  wj.lo[6] = pWvl;  wj.K[6] = DG;  wj.Kpad[6] = DG;  wj.total[6] = DG * DG;
    convert_batch<<<dim3(2048, 7), 256>>>(wj);

    // 4: Ul = U @ W_l^T + b_l -> bf16 pair
    gemm_mma<2><<<dim3(4, 48), 256, GEMM_SMEM>>>(pUhi, pUlo, pWlh, pWll, b_l, nullptr,
                                                 nullptr, pXhi, pXlo, 1024, 512, 0);
    // 5: layer-0 x gates (f+b fused, transposed output)
    gemm_xg<<<dim3(8, 48, 2), 256, GEMM_SMEM>>>(pXhi, pXlo, pW0fh, pW0fl, pW0bh, pW0bl,
                                                bih0f, bhh0f, bih0b, bhh0b, pxf, pxb, 512);
    // 6: LSTM layer 0 (profiled) -> bf16 pair
    lstm_kernel<<<128, 256, LSTM_SMEM>>>(pxf, pxb, Whh0f, Whh0b, nullptr, pYhi, pYlo, 0);

    // 7: input conversions (U_a padded, U_v)
    CJobs ij;
    ij.in[0] = U_a; ij.hi[0] = pUah; ij.lo[0] = pUal; ij.K[0] = 100; ij.Kpad[0] = 128; ij.total[0] = TB * 128;
    ij.in[1] = U_v; ij.hi[1] = pUvh; ij.lo[1] = pUvl; ij.K[1] = DG;  ij.Kpad[1] = DG;  ij.total[1] = TB * DG;
    convert_batch<<<dim3(TB * DG / 256, 2), 256>>>(ij);

    // 8-9: emotions_a / emotions_v -> out (graphify)
    gemm_mma<1><<<dim3(4, 48), 256, GEMM_SMEM>>>(pUah, pUal, pWah, pWal, b_a, nullptr,
                                                 out, nullptr, nullptr, 128, 1536, 0);
    gemm_mma<1><<<dim3(4, 48), 256, GEMM_SMEM>>>(pUvh, pUvl, pWvh, pWvl, b_v, nullptr,
                                                 out, nullptr, nullptr, 512, 1536, 512);
    // 10: layer-1 x gates
    gemm_xg<<<dim3(8, 48, 2), 256, GEMM_SMEM>>>(pYhi, pYlo, pW1fh, pW1fl, pW1bh, pW1bl,
                                                bih1f, bhh1f, bih1b, bhh1b, pxf, pxb, 512);
    // 11: LSTM layer 1 -> out
    lstm_kernel<<<128, 256, LSTM_SMEM>>>(pxf, pxb, Whh1f, Whh1b, out, nullptr, nullptr, 1);
}

// round 6
// speedup vs baseline: 1.6758x; 1.0182x over previous
#include <cuda_runtime.h>
#include <cuda_bf16.h>
#include <math.h>
#include <stdint.h>

// ---------------- problem constants ----------------
#define Tt   96
#define Bb   64
#define TB   6144
#define DM   1024
#define DG   512
#define HH   256
#define G4   1024

// ---------------- scratch ----------------
__device__ float g_xgf[TB * G4];      // transposed [t][col][b]
__device__ float g_xgb[TB * G4];
__device__ float g_alpha[4 * Bb];
__device__ float g_shift[4 * Bb];

__device__ __nv_bfloat16 g_Uhi[TB * DM],  g_Ulo[TB * DM];
__device__ __nv_bfloat16 g_Uah[TB * 128], g_Ual[TB * 128];
__device__ __nv_bfloat16 g_Uvh[TB * DG],  g_Uvl[TB * DG];
__device__ __nv_bfloat16 g_Xhi[TB * DG],  g_Xlo[TB * DG];
__device__ __nv_bfloat16 g_Yhi[TB * DG],  g_Ylo[TB * DG];
__device__ __nv_bfloat16 g_Wah[DG * 128], g_Wal[DG * 128];
__device__ __nv_bfloat16 g_Wvh[DG * DG],  g_Wvl[DG * DG];
__device__ __nv_bfloat16 g_Wlh[DG * DM],  g_Wll[DG * DM];
__device__ __nv_bfloat16 g_W0fh[G4 * DG], g_W0fl[G4 * DG];
__device__ __nv_bfloat16 g_W0bh[G4 * DG], g_W0bl[G4 * DG];
__device__ __nv_bfloat16 g_W1fh[G4 * DG], g_W1fl[G4 * DG];
__device__ __nv_bfloat16 g_W1bh[G4 * DG], g_W1bl[G4 * DG];

// ---------------- helpers ----------------
__device__ __forceinline__ uint32_t smem_u32(const void* p) {
    uint32_t a;
    asm("{ .reg .u64 t; cvta.to.shared.u64 t, %1; cvt.u32.u64 %0, t; }" : "=r"(a) : "l"(p));
    return a;
}
__device__ __forceinline__ uint32_t lds32(uint32_t addr) {
    uint32_t v;
    asm volatile("ld.shared.b32 %0, [%1];" : "=r"(v) : "r"(addr));
    return v;
}
#define CP16(dst, src) \
    asm volatile("cp.async.cg.shared.global [%0], [%1], 16;" :: "r"(dst), "l"(src))
#define CP_COMMIT() asm volatile("cp.async.commit_group;" ::: "memory")
#define CP_WAIT(n)  asm volatile("cp.async.wait_group %0;" :: "n"(n) : "memory")

#define MMA16816(d, a, b) \
    asm volatile("mma.sync.aligned.m16n8k16.row.col.f32.bf16.bf16.f32 " \
        "{%0,%1,%2,%3}, {%4,%5,%6,%7}, {%8,%9}, {%0,%1,%2,%3};" \
        : "+f"((d)[0]), "+f"((d)[1]), "+f"((d)[2]), "+f"((d)[3]) \
        : "r"((a)[0]), "r"((a)[1]), "r"((a)[2]), "r"((a)[3]), "r"((b)[0]), "r"((b)[1]))

// ---------------- LN2 statistics ----------------
__global__ void stats_kernel(const float* __restrict__ r1, const float* __restrict__ r2,
                             const float* __restrict__ r3, const float* __restrict__ r4)
{
    int i = blockIdx.x >> 6;
    int b = blockIdx.x & 63;
    const float* r = (i == 0) ? r1 : (i == 1) ? r2 : (i == 2) ? r3 : r4;
    float s = 0.f, q = 0.f;
    const float4* base = (const float4*)(r + (size_t)b * DM);
    for (int t = 0; t < Tt; t++) {
        float4 v = base[(size_t)t * (Bb * DM / 4) + threadIdx.x];
        s += v.x + v.y + v.z + v.w;
        q += v.x * v.x + v.y * v.y + v.z * v.z + v.w * v.w;
    }
    __shared__ float ss[256], sq[256];
    ss[threadIdx.x] = s; sq[threadIdx.x] = q;
    __syncthreads();
    for (int st = 128; st > 0; st >>= 1) {
        if (threadIdx.x < st) { ss[threadIdx.x] += ss[threadIdx.x + st]; sq[threadIdx.x] += sq[threadIdx.x + st]; }
        __syncthreads();
    }
    if (threadIdx.x == 0) {
        const float inv_n = 1.f / (float)(Tt * DM);
        float m   = ss[0] * inv_n;
        float var = sq[0] * inv_n - m * m;
        float a   = 0.25f * rsqrtf(var + 1e-5f);
        g_alpha[i * Bb + b] = a;
        g_shift[i * Bb + b] = a * m;
    }
}

// ---------------- fused U build + bf16 split ----------------
__global__ void build_u_split(const float* __restrict__ r1, const float* __restrict__ r2,
                              const float* __restrict__ r3, const float* __restrict__ r4)
{
    size_t idx = (size_t)blockIdx.x * blockDim.x + threadIdx.x;
    size_t e   = idx * 4;
    int b = (int)((e >> 10) & 63);
    float a1 = g_alpha[b], a2 = g_alpha[64 + b], a3 = g_alpha[128 + b], a4 = g_alpha[192 + b];
    float sh = g_shift[b] + g_shift[64 + b] + g_shift[128 + b] + g_shift[192 + b];
    float4 v1 = ((const float4*)r1)[idx];
    float4 v2 = ((const float4*)r2)[idx];
    float4 v3 = ((const float4*)r3)[idx];
    float4 v4 = ((const float4*)r4)[idx];
    float o[4];
    o[0] = a1 * v1.x + a2 * v2.x + a3 * v3.x + a4 * v4.x - sh;
    o[1] = a1 * v1.y + a2 * v2.y + a3 * v3.y + a4 * v4.y - sh;
    o[2] = a1 * v1.z + a2 * v2.z + a3 * v3.z + a4 * v4.z - sh;
    o[3] = a1 * v1.w + a2 * v2.w + a3 * v3.w + a4 * v4.w - sh;
    __nv_bfloat162 hi0, hi1, lo0, lo1;
    hi0.x = __float2bfloat16(o[0]); hi0.y = __float2bfloat16(o[1]);
    hi1.x = __float2bfloat16(o[2]); hi1.y = __float2bfloat16(o[3]);
    lo0.x = __float2bfloat16(o[0] - __bfloat162float(hi0.x));
    lo0.y = __float2bfloat16(o[1] - __bfloat162float(hi0.y));
    lo1.x = __float2bfloat16(o[2] - __bfloat162float(hi1.x));
    lo1.y = __float2bfloat16(o[3] - __bfloat162float(hi1.y));
    ((__nv_bfloat162*)g_Uhi)[idx * 2]     = hi0;
    ((__nv_bfloat162*)g_Uhi)[idx * 2 + 1] = hi1;
    ((__nv_bfloat162*)g_Ulo)[idx * 2]     = lo0;
    ((__nv_bfloat162*)g_Ulo)[idx * 2 + 1] = lo1;
}

// ---------------- batched fp32 -> bf16 hi/lo ----------------
struct CJobs {
    const float*   in[7];
    __nv_bfloat16* hi[7];
    __nv_bfloat16* lo[7];
    int K[7], Kpad[7], total[7];
};
__global__ void convert_batch(CJobs j)
{
    int job = blockIdx.y;
    int idx = blockIdx.x * 256 + threadIdx.x;
    if (idx >= j.total[job]) return;
    int K = j.K[job], Kp = j.Kpad[job];
    int r = idx / Kp, c = idx - r * Kp;
    float v = (c < K) ? j.in[job][(size_t)r * K + c] : 0.f;
    __nv_bfloat16 h = __float2bfloat16(v);
    j.hi[job][idx] = h;
    j.lo[job][idx] = __float2bfloat16(v - __bfloat162float(h));
}

// ---------------- bf16-split GEMM, 128x64 tile, 3-stage, 2 CTA/SM ----------------
#define RSTRIDE 80                         // padded row stride bytes (40 bf16)
#define ATSZ    (128 * RSTRIDE)            // 10240
#define BTSZ    (64 * RSTRIDE)             // 5120
#define STG_SZ  (2 * ATSZ + 2 * BTSZ)      // 30720
#define SM_TILES 256
#define GEMM_SMEM (SM_TILES + 3 * STG_SZ)  // 92416

#define GEMM_PROLOG() \
    extern __shared__ char smem[]; \
    const uint32_t sb = smem_u32(smem); \
    const int tid  = threadIdx.x; \
    const int lane = tid & 31, wid = tid >> 5; \
    const int wm = wid >> 1, wn = wid & 1; \
    const int g = lane >> 2, tig = lane & 3; \
    const int n0 = blockIdx.x * 64, m0 = blockIdx.y * 128; \
    float acc[2][4][4]; \
    _Pragma("unroll") for (int i = 0; i < 2; i++) \
    _Pragma("unroll") for (int jj = 0; jj < 4; jj++) \
    _Pragma("unroll") for (int x = 0; x < 4; x++) acc[i][jj][x] = 0.f;

#define LOAD_STAGE(st, ch) do { \
    int kc = (ch) << 5; \
    uint32_t stg = sb + SM_TILES + (st) * STG_SZ; \
    { int r = (tid * 2) >> 2, q = (tid * 2) & 3; \
      size_t off = (size_t)(m0 + r) * K + kc + q * 8; \
      uint32_t d = stg + r * RSTRIDE + q * 16; \
      CP16(d, Ahi + off); CP16(d + ATSZ, Alo + off); } \
    { int r = (tid * 2 + 1) >> 2, q = (tid * 2 + 1) & 3; \
      size_t off = (size_t)(m0 + r) * K + kc + q * 8; \
      uint32_t d = stg + r * RSTRIDE + q * 16; \
      CP16(d, Ahi + off); CP16(d + ATSZ, Alo + off); } \
    { int r = tid >> 2, q = tid & 3; \
      size_t off = (size_t)(n0 + r) * K + kc + q * 8; \
      uint32_t d = stg + 2 * ATSZ + r * RSTRIDE + q * 16; \
      CP16(d, Bhi + off); CP16(d + BTSZ, Blo + off); } \
    CP_COMMIT(); \
} while (0)

#define COMPUTE_STAGE(st) do { \
    uint32_t stg = sb + SM_TILES + (st) * STG_SZ; \
    uint32_t sAh = stg, sAl = stg + ATSZ, sBh = stg + 2 * ATSZ, sBl = stg + 2 * ATSZ + BTSZ; \
    _Pragma("unroll") \
    for (int kh = 0; kh < 2; kh++) { \
        const uint32_t col0 = (kh * 16 + 2 * tig) * 2; \
        uint32_t ah[2][4], al[2][4], bh[4][2], bl[4][2]; \
        _Pragma("unroll") \
        for (int mt = 0; mt < 2; mt++) { \
            uint32_t r0a = (uint32_t)(wm * 32 + mt * 16 + g) * RSTRIDE + col0; \
            uint32_t r1a = r0a + 8 * RSTRIDE; \
            ah[mt][0] = lds32(sAh + r0a);      ah[mt][1] = lds32(sAh + r1a); \
            ah[mt][2] = lds32(sAh + r0a + 16); ah[mt][3] = lds32(sAh + r1a + 16); \
            al[mt][0] = lds32(sAl + r0a);      al[mt][1] = lds32(sAl + r1a); \
            al[mt][2] = lds32(sAl + r0a + 16); al[mt][3] = lds32(sAl + r1a + 16); \
        } \
        _Pragma("unroll") \
        for (int nt = 0; nt < 4; nt++) { \
            uint32_t rb = (uint32_t)(wn * 32 + nt * 8 + g) * RSTRIDE + col0; \
            bh[nt][0] = lds32(sBh + rb); bh[nt][1] = lds32(sBh + rb + 16); \
            bl[nt][0] = lds32(sBl + rb); bl[nt][1] = lds32(sBl + rb + 16); \
        } \
        _Pragma("unroll") \
        for (int mt = 0; mt < 2; mt++) \
        _Pragma("unroll") \
            for (int nt = 0; nt < 4; nt++) MMA16816(acc[mt][nt], ah[mt], bh[nt]); \
        _Pragma("unroll") \
        for (int mt = 0; mt < 2; mt++) \
        _Pragma("unroll") \
            for (int nt = 0; nt < 4; nt++) MMA16816(acc[mt][nt], ah[mt], bl[nt]); \
        _Pragma("unroll") \
        for (int mt = 0; mt < 2; mt++) \
        _Pragma("unroll") \
            for (int nt = 0; nt < 4; nt++) MMA16816(acc[mt][nt], al[mt], bh[nt]); \
    } \
} while (0)

#define GEMM_MAINLOOP() \
    const int nch = K >> 5; \
    LOAD_STAGE(0, 0); \
    LOAD_STAGE(1, 1); \
    for (int ch = 0; ch < nch; ch++) { \
        const int st = ch % 3; \
        if (ch + 2 < nch) { CP_WAIT(1); } else { CP_WAIT(0); } \
        __syncthreads(); \
        if (ch + 2 < nch) LOAD_STAGE((ch + 2) % 3, ch + 2); \
        COMPUTE_STAGE(st); \
        __syncthreads(); \
    }

// OUTMODE: 1 = fp32 graphify into d_out, 2 = bf16 hi/lo pair
template <int OUTMODE>
__global__ void __launch_bounds__(256, 2) gemm_mma(
    const __nv_bfloat16* __restrict__ Ahi, const __nv_bfloat16* __restrict__ Alo,
    const __nv_bfloat16* __restrict__ Bhi, const __nv_bfloat16* __restrict__ Blo,
    const float* __restrict__ bias1,
    float* __restrict__ C, __nv_bfloat16* __restrict__ Chi, __nv_bfloat16* __restrict__ Clo,
    int K, int ldc, int coloff)
{
    GEMM_PROLOG();
    __shared__ float sBias[64];
    if (tid < 64) sBias[tid] = bias1[n0 + tid];
    GEMM_MAINLOOP();

#pragma unroll
    for (int mt = 0; mt < 2; mt++) {
        const int r0 = m0 + wm * 32 + mt * 16 + g;
        const int r1 = r0 + 8;
#pragma unroll
        for (int nt = 0; nt < 4; nt++) {
            const int cb = wn * 32 + nt * 8 + 2 * tig;
            const float b0v = sBias[cb], b1v = sBias[cb + 1];
            float v00 = acc[mt][nt][0] + b0v, v01 = acc[mt][nt][1] + b1v;
            float v10 = acc[mt][nt][2] + b0v, v11 = acc[mt][nt][3] + b1v;
            if (OUTMODE == 2) {
                __nv_bfloat162 h0, l0, h1, l1;
                h0.x = __float2bfloat16(v00); h0.y = __float2bfloat16(v01);
                l0.x = __float2bfloat16(v00 - __bfloat162float(h0.x));
                l0.y = __float2bfloat16(v01 - __bfloat162float(h0.y));
                h1.x = __float2bfloat16(v10); h1.y = __float2bfloat16(v11);
                l1.x = __float2bfloat16(v10 - __bfloat162float(h1.x));
                l1.y = __float2bfloat16(v11 - __bfloat162float(h1.y));
                size_t o0 = (size_t)r0 * ldc + n0 + cb;
                size_t o1 = (size_t)r1 * ldc + n0 + cb;
                *(__nv_bfloat162*)(Chi + o0) = h0;
                *(__nv_bfloat162*)(Clo + o0) = l0;
                *(__nv_bfloat162*)(Chi + o1) = h1;
                *(__nv_bfloat162*)(Clo + o1) = l1;
            } else {
                int row0 = (r0 & 63) * Tt + (r0 >> 6);
                int row1 = (r1 & 63) * Tt + (r1 >> 6);
                *(float2*)(C + (size_t)row0 * ldc + coloff + n0 + cb) = make_float2(v00, v01);
                *(float2*)(C + (size_t)row1 * ldc + coloff + n0 + cb) = make_float2(v10, v11);
            }
        }
    }
}

// xg GEMM: blockIdx.z = dir; output transposed [t][col][b]
__global__ void __launch_bounds__(256, 2) gemm_xg(
    const __nv_bfloat16* __restrict__ Ahi, const __nv_bfloat16* __restrict__ Alo,
    const __nv_bfloat16* __restrict__ Bfh, const __nv_bfloat16* __restrict__ Bfl,
    const __nv_bfloat16* __restrict__ Bbh, const __nv_bfloat16* __restrict__ Bbl,
    const float* __restrict__ bf1, const float* __restrict__ bf2,
    const float* __restrict__ bb1, const float* __restrict__ bb2,
    float* __restrict__ Cf, float* __restrict__ Cb, int K)
{
    const __nv_bfloat16* Bhi = blockIdx.z ? Bbh : Bfh;
    const __nv_bfloat16* Blo = blockIdx.z ? Bbl : Bfl;
    const float* bias1 = blockIdx.z ? bb1 : bf1;
    const float* bias2 = blockIdx.z ? bb2 : bf2;
    float* C = blockIdx.z ? Cb : Cf;

    GEMM_PROLOG();
    __shared__ float sBias[64];
    if (tid < 64) sBias[tid] = bias1[n0 + tid] + bias2[n0 + tid];
    GEMM_MAINLOOP();

#pragma unroll
    for (int mt = 0; mt < 2; mt++) {
        const int r0 = m0 + wm * 32 + mt * 16 + g;
        const int r1 = r0 + 8;
        const int t0 = r0 >> 6, b0r = r0 & 63;
        const int t1 = r1 >> 6, b1r = r1 & 63;
#pragma unroll
        for (int nt = 0; nt < 4; nt++) {
            const int cb = wn * 32 + nt * 8 + 2 * tig;
            const float b0v = sBias[cb], b1v = sBias[cb + 1];
            float* p0 = C + (size_t)t0 * (Bb * G4) + (size_t)(n0 + cb) * Bb;
            float* p1 = C + (size_t)t1 * (Bb * G4) + (size_t)(n0 + cb) * Bb;
            p0[b0r]      = acc[mt][nt][0] + b0v;
            p0[Bb + b0r] = acc[mt][nt][1] + b1v;
            p1[b1r]      = acc[mt][nt][2] + b0v;
            p1[Bb + b1r] = acc[mt][nt][3] + b1v;
        }
    }
}

// ---------------- cluster-based bidirectional LSTM ----------------
#define SW_FLOATS (256 * 33 * 4)
#define SH_FLOATS (2 * 2048)
#define LSTM_SMEM ((SW_FLOATS + SH_FLOATS) * 4)

#define CLUSTER_SYNC() do { \
    asm volatile("barrier.cluster.arrive.aligned;" ::: "memory"); \
    asm volatile("barrier.cluster.wait.aligned;"   ::: "memory"); \
} while (0)

__global__ void __launch_bounds__(256, 1) __cluster_dims__(8, 1, 1)
lstm_kernel(const float* __restrict__ xgf, const float* __restrict__ xgb,
            const float* __restrict__ Whhf, const float* __restrict__ Whhb,
            float* __restrict__ outp,
            __nv_bfloat16* __restrict__ Chi, __nv_bfloat16* __restrict__ Clo,
            int mode)
{
    extern __shared__ float smemf[];
    float4* sW = (float4*)smemf;
    float*  sH = smemf + SW_FLOATS;

    const int tid  = threadIdx.x;
    const int lane = tid & 31;
    uint32_t rank;
    asm("mov.u32 %0, %%cluster_ctarank;" : "=r"(rank));
    const int dir  = blockIdx.x >> 6;
    const int bgrp = (blockIdx.x >> 3) & 7;
    const int b    = tid & 7;
    const int u    = tid >> 3;
    const int n    = (int)rank * 32 + u;
    const int bglob = bgrp * 8 + b;

    const float* xg  = dir ? xgb : xgf;
    const float* Whh = dir ? Whhb : Whhf;

#pragma unroll 4
    for (int it = 0; it < 32; it++) {
        int idx = it * 256 + tid;
        int uu  = (idx >> 3) & 31;
        int kk  = (idx & 7) | ((idx >> 8) << 3);
        int nn  = (int)rank * 32 + uu;
        float4 w;
        w.x = Whh[(size_t)(       nn) * HH + kk];
        w.y = Whh[(size_t)(HH   + nn) * HH + kk];
        w.z = Whh[(size_t)(2*HH + nn) * HH + kk];
        w.w = Whh[(size_t)(3*HH + nn) * HH + kk];
        sW[kk * 33 + uu] = w;
    }
    for (int i = tid; i < SH_FLOATS; i += 256) sH[i] = 0.f;

    const uint32_t sm_base = smem_u32(smemf);

    CLUSTER_SYNC();

    float c = 0.f;
    for (int step = 0; step < Tt; step++) {
        const int t    = dir ? (Tt - 1 - step) : step;
        const int rbuf = step & 1;
        const int wbuf = rbuf ^ 1;

        const float* xp = xg + (size_t)t * (Bb * G4) + (size_t)n * Bb + bglob;
        float xi  = xp[0];
        float xf  = xp[HH * Bb];
        float xgv = xp[2 * HH * Bb];
        float xo  = xp[3 * HH * Bb];

        const float*  hp = sH + rbuf * 2048 + b;
        const float4* wp = sW + u;

        // four independent f32x2 accumulator chains (even/odd k)
        unsigned long long aIF0 = 0ull, aGO0 = 0ull, aIF1 = 0ull, aGO1 = 0ull;
#pragma unroll 16
        for (int k = 0; k < HH; k += 2) {
            float h0 = hp[k * 8];
            float h1 = hp[(k + 1) * 8];
            longlong2 w0 = *(const longlong2*)(wp + k * 33);
            longlong2 w1 = *(const longlong2*)(wp + (k + 1) * 33);
            unsigned hb0 = __float_as_uint(h0), hb1 = __float_as_uint(h1);
            unsigned long long hh0, hh1;
            asm("mov.b64 %0, {%1, %1};" : "=l"(hh0) : "r"(hb0));
            asm("mov.b64 %0, {%1, %1};" : "=l"(hh1) : "r"(hb1));
            asm("fma.rn.f32x2 %0, %1, %2, %0;" : "+l"(aIF0) : "l"(hh0), "l"((unsigned long long)w0.x));
            asm("fma.rn.f32x2 %0, %1, %2, %0;" : "+l"(aGO0) : "l"(hh0), "l"((unsigned long long)w0.y));
            asm("fma.rn.f32x2 %0, %1, %2, %0;" : "+l"(aIF1) : "l"(hh1), "l"((unsigned long long)w1.x));
            asm("fma.rn.f32x2 %0, %1, %2, %0;" : "+l"(aGO1) : "l"(hh1), "l"((unsigned long long)w1.y));
        }
        unsigned ri0, rf0, rg0, ro0, ri1, rf1, rg1, ro1;
        asm("mov.b64 {%0, %1}, %2;" : "=r"(ri0), "=r"(rf0) : "l"(aIF0));
        asm("mov.b64 {%0, %1}, %2;" : "=r"(rg0), "=r"(ro0) : "l"(aGO0));
        asm("mov.b64 {%0, %1}, %2;" : "=r"(ri1), "=r"(rf1) : "l"(aIF1));
        asm("mov.b64 {%0, %1}, %2;" : "=r"(rg1), "=r"(ro1) : "l"(aGO1));

        float gi = __uint_as_float(ri0) + __uint_as_float(ri1) + xi;
        float gf = __uint_as_float(rf0) + __uint_as_float(rf1) + xf;
        float gg = __uint_as_float(rg0) + __uint_as_float(rg1) + xgv;
        float go = __uint_as_float(ro0) + __uint_as_float(ro1) + xo;
        float si = 1.f / (1.f + expf(-gi));
        float sf = 1.f / (1.f + expf(-gf));
        float so = 1.f / (1.f + expf(-go));
        c = sf * c + si * tanhf(gg);
        float h = so * tanhf(c);

        // DSMEM broadcast FIRST (critical path), then local output store
        float4 p;
        int lb = lane & ~3;
        p.x = __shfl_sync(0xffffffffu, h, lb);
        p.y = __shfl_sync(0xffffffffu, h, lb + 1);
        p.z = __shfl_sync(0xffffffffu, h, lb + 2);
        p.w = __shfl_sync(0xffffffffu, h, lb + 3);
        if ((b & 3) == 0) {
            uint32_t dst = sm_base + (uint32_t)(SW_FLOATS + wbuf * 2048 + n * 8 + b) * 4u;
#pragma unroll
            for (int r2 = 0; r2 < 8; r2++) {
                uint32_t ra;
                asm("mapa.shared::cluster.u32 %0, %1, %2;" : "=r"(ra) : "r"(dst), "r"(r2));
                asm volatile("st.shared::cluster.v4.f32 [%0], {%1, %2, %3, %4};"
                             :: "r"(ra), "f"(p.x), "f"(p.y), "f"(p.z), "f"(p.w));
            }
        }

        if (mode == 0) {
            size_t o = ((size_t)t * Bb + bglob) * DG + dir * HH + n;
            __nv_bfloat16 hh16 = __float2bfloat16(h);
            Chi[o] = hh16;
            Clo[o] = __float2bfloat16(h - __bfloat162float(hh16));
        } else {
            int row = bglob * Tt + t;
            outp[(size_t)row * 1536 + 1024 + dir * HH + n] = h;
        }
        CLUSTER_SYNC();
    }
}

// ---------------- launch ----------------
extern "C" void kernel_launch(void* const* d_in, const int* in_sizes, int n_in,
                              void* d_out, int out_size)
{
    const float* r1  = (const float*)d_in[0];
    const float* r2  = (const float*)d_in[1];
    const float* r3  = (const float*)d_in[2];
    const float* r4  = (const float*)d_in[3];
    const float* U_a = (const float*)d_in[4];
    const float* U_v = (const float*)d_in[5];
    const float* W_a = (const float*)d_in[7];
    const float* b_a = (const float*)d_in[8];
    const float* W_v = (const float*)d_in[9];
    const float* b_v = (const float*)d_in[10];
    const float* W_l = (const float*)d_in[11];
    const float* b_l = (const float*)d_in[12];
    const float* Wih0f = (const float*)d_in[13];
    const float* Whh0f = (const float*)d_in[14];
    const float* bih0f = (const float*)d_in[15];
    const float* bhh0f = (const float*)d_in[16];
    const float* Wih0b = (const float*)d_in[17];
    const float* Whh0b = (const float*)d_in[18];
    const float* bih0b = (const float*)d_in[19];
    const float* bhh0b = (const float*)d_in[20];
    const float* Wih1f = (const float*)d_in[21];
    const float* Whh1f = (const float*)d_in[22];
    const float* bih1f = (const float*)d_in[23];
    const float* bhh1f = (const float*)d_in[24];
    const float* Wih1b = (const float*)d_in[25];
    const float* Whh1b = (const float*)d_in[26];
    const float* bih1b = (const float*)d_in[27];
    const float* bhh1b = (const float*)d_in[28];
    float* out = (float*)d_out;

    float *pxf, *pxb;
    cudaGetSymbolAddress((void**)&pxf, g_xgf);
    cudaGetSymbolAddress((void**)&pxb, g_xgb);
    __nv_bfloat16 *pUhi, *pUlo, *pUah, *pUal, *pUvh, *pUvl, *pXhi, *pXlo, *pYhi, *pYlo;
    __nv_bfloat16 *pWah, *pWal, *pWvh, *pWvl, *pWlh, *pWll;
    __nv_bfloat16 *pW0fh, *pW0fl, *pW0bh, *pW0bl, *pW1fh, *pW1fl, *pW1bh, *pW1bl;
    cudaGetSymbolAddress((void**)&pUhi, g_Uhi); cudaGetSymbolAddress((void**)&pUlo, g_Ulo);
    cudaGetSymbolAddress((void**)&pUah, g_Uah); cudaGetSymbolAddress((void**)&pUal, g_Ual);
    cudaGetSymbolAddress((void**)&pUvh, g_Uvh); cudaGetSymbolAddress((void**)&pUvl, g_Uvl);
    cudaGetSymbolAddress((void**)&pXhi, g_Xhi); cudaGetSymbolAddress((void**)&pXlo, g_Xlo);
    cudaGetSymbolAddress((void**)&pYhi, g_Yhi); cudaGetSymbolAddress((void**)&pYlo, g_Ylo);
    cudaGetSymbolAddress((void**)&pWah, g_Wah); cudaGetSymbolAddress((void**)&pWal, g_Wal);
    cudaGetSymbolAddress((void**)&pWvh, g_Wvh); cudaGetSymbolAddress((void**)&pWvl, g_Wvl);
    cudaGetSymbolAddress((void**)&pWlh, g_Wlh); cudaGetSymbolAddress((void**)&pWll, g_Wll);
    cudaGetSymbolAddress((void**)&pW0fh, g_W0fh); cudaGetSymbolAddress((void**)&pW0fl, g_W0fl);
    cudaGetSymbolAddress((void**)&pW0bh, g_W0bh); cudaGetSymbolAddress((void**)&pW0bl, g_W0bl);
    cudaGetSymbolAddress((void**)&pW1fh, g_W1fh); cudaGetSymbolAddress((void**)&pW1fl, g_W1fl);
    cudaGetSymbolAddress((void**)&pW1bh, g_W1bh); cudaGetSymbolAddress((void**)&pW1bl, g_W1bl);

    cudaFuncSetAttribute(gemm_mma<1>, cudaFuncAttributeMaxDynamicSharedMemorySize, GEMM_SMEM);
    cudaFuncSetAttribute(gemm_mma<2>, cudaFuncAttributeMaxDynamicSharedMemorySize, GEMM_SMEM);
    cudaFuncSetAttribute(gemm_xg,     cudaFuncAttributeMaxDynamicSharedMemorySize, GEMM_SMEM);
    cudaFuncSetAttribute(lstm_kernel, cudaFuncAttributeMaxDynamicSharedMemorySize, LSTM_SMEM);

    stats_kernel<<<256, 256>>>(r1, r2, r3, r4);
    build_u_split<<<TB * DM / 4 / 256, 256>>>(r1, r2, r3, r4);

    CJobs wj;
    wj.in[0] = W_l;   wj.hi[0] = pWlh;  wj.lo[0] = pWll;  wj.K[0] = DM;  wj.Kpad[0] = DM;  wj.total[0] = DG * DM;
    wj.in[1] = Wih0f; wj.hi[1] = pW0fh; wj.lo[1] = pW0fl; wj.K[1] = DG;  wj.Kpad[1] = DG;  wj.total[1] = G4 * DG;
    wj.in[2] = Wih0b; wj.hi[2] = pW0bh; wj.lo[2] = pW0bl; wj.K[2] = DG;  wj.Kpad[2] = DG;  wj.total[2] = G4 * DG;
    wj.in[3] = Wih1f; wj.hi[3] = pW1fh; wj.lo[3] = pW1fl; wj.K[3] = DG;  wj.Kpad[3] = DG;  wj.total[3] = G4 * DG;
    wj.in[4] = Wih1b; wj.hi[4] = pW1bh; wj.lo[4] = pW1bl; wj.K[4] = DG;  wj.Kpad[4] = DG;  wj.total[4] = G4 * DG;
    wj.in[5] = W_a;   wj.hi[5] = pWah;  wj.lo[5] = pWal;  wj.K[5] = 100; wj.Kpad[5] = 128; wj.total[5] = DG * 128;
    wj.in[6] = W_v;   wj.hi[6] = pWvh;  wj.lo[6] = pWvl;  wj.K[6] = DG;  wj.Kpad[6] = DG;  wj.total[6] = DG * DG;
    convert_batch<<<dim3(2048, 7), 256>>>(wj);

    // Ul = U @ W_l^T + b_l -> bf16 pair
    gemm_mma<2><<<dim3(8, 48), 256, GEMM_SMEM>>>(pUhi, pUlo, pWlh, pWll, b_l,
                                                 nullptr, pXhi, pXlo, 1024, 512, 0);
    // layer-0 x gates (f+b, transposed out)
    gemm_xg<<<dim3(16, 48, 2), 256, GEMM_SMEM>>>(pXhi, pXlo, pW0fh, pW0fl, pW0bh, pW0bl,
                                                 bih0f, bhh0f, bih0b, bhh0b, pxf, pxb, 512);
    // LSTM layer 0 -> bf16 pair
    lstm_kernel<<<128, 256, LSTM_SMEM>>>(pxf, pxb, Whh0f, Whh0b, nullptr, pYhi, pYlo, 0);

    CJobs ij;
    ij.in[0] = U_a; ij.hi[0] = pUah; ij.lo[0] = pUal; ij.K[0] = 100; ij.Kpad[0] = 128; ij.total[0] = TB * 128;
    ij.in[1] = U_v; ij.hi[1] = pUvh; ij.lo[1] = pUvl; ij.K[1] = DG;  ij.Kpad[1] = DG;  ij.total[1] = TB * DG;
    convert_batch<<<dim3(TB * DG / 256, 2), 256>>>(ij);

    gemm_mma<1><<<dim3(8, 48), 256, GEMM_SMEM>>>(pUah, pUal, pWah, pWal, b_a,
                                                 out, nullptr, nullptr, 128, 1536, 0);
    gemm_mma<1><<<dim3(8, 48), 256, GEMM_SMEM>>>(pUvh, pUvl, pWvh, pWvl, b_v,
                                                 out, nullptr, nullptr, 512, 1536, 512);
    gemm_xg<<<dim3(16, 48, 2), 256, GEMM_SMEM>>>(pYhi, pYlo, pW1fh, pW1fl, pW1bh, pW1bl,
                                                 bih1f, bhh1f, bih1b, bhh1b, pxf, pxb, 512);
    lstm_kernel<<<128, 256, LSTM_SMEM>>>(pxf, pxb, Whh1f, Whh1b, out, nullptr, nullptr, 1);
}